// round 9
// baseline (speedup 1.0000x reference)
#include <cuda_runtime.h>
#include <cuda_bf16.h>
#include <math.h>
#include <stdint.h>

#define Nn   50000
#define Ee   200000
#define EP   (Ee + Nn)      // 250000 edges incl. self loops
#define Gg   64
#define Hh   4
#define Cch  256
#define DH   1024
#define DIN  768

// ---------------- scratch (device globals; no allocation allowed) ----------
__device__ float g_h  [(size_t)Nn * DH];   // x @ W  (current layer)
__device__ float g_x  [(size_t)Nn * DH];   // layer output (post ELU)
__device__ float g_acc[(size_t)Nn * DH];   // segment-sum accumulator
__device__ float g_esrc[Nn * Hh];
__device__ float g_edst[Nn * Hh];
__device__ float g_m   [Nn * Hh];
__device__ float g_s   [Nn * Hh];
__device__ float g_e   [EP * Hh];          // edge logits, then p=exp(e-m)
__device__ float g_sum [Gg * DH];
__device__ float g_max [Gg * DH];
__device__ int   g_cnt [Gg];
__device__ float g_pool[Gg * 2 * DH];
__device__ float g_fc1 [Gg * 512];
__device__ float g_fc2 [Gg * 256];
// transposed + hi/lo split weights for tensor-core GEMM: Wt[n][k]
__device__ __nv_bfloat16 g_wthi[(size_t)DH * DH];
__device__ __nv_bfloat16 g_wtlo[(size_t)DH * DH];

// ---------------- helpers ---------------------------------------------------
__device__ __forceinline__ float lrelu(float x) { return x > 0.f ? x : 0.2f * x; }
__device__ __forceinline__ float eluf (float x) { return x > 0.f ? x : expm1f(x); }

__device__ __forceinline__ void atomicMaxF(float* a, float v) {
    if (v >= 0.f) atomicMax((int*)a, __float_as_int(v));
    else          atomicMin((unsigned int*)a, __float_as_uint(v));
}

__device__ __forceinline__ void redAdd4(float* p, float4 v) {
    asm volatile("red.global.add.v4.f32 [%0], {%1,%2,%3,%4};"
                 :: "l"(p), "f"(v.x), "f"(v.y), "f"(v.z), "f"(v.w) : "memory");
}

__device__ __forceinline__ uint32_t smem_u32(const void* p) {
    uint32_t a;
    asm("{ .reg .u64 t; cvta.to.shared.u64 t, %1; cvt.u32.u64 %0, t; }"
        : "=r"(a) : "l"(p));
    return a;
}

#define SWZ(o) ((o) ^ (((o) >> 3) & 0x70))

__device__ __forceinline__ void ldm4(uint32_t* r, uint32_t addr) {
    asm volatile("ldmatrix.sync.aligned.m8n8.x4.shared.b16 {%0,%1,%2,%3}, [%4];"
                 : "=r"(r[0]), "=r"(r[1]), "=r"(r[2]), "=r"(r[3]) : "r"(addr));
}

__device__ __forceinline__ void mma16816(float* c, const uint32_t* a,
                                         uint32_t b0, uint32_t b1) {
    asm volatile(
        "mma.sync.aligned.m16n8k16.row.col.f32.bf16.bf16.f32 "
        "{%0,%1,%2,%3}, {%4,%5,%6,%7}, {%8,%9}, {%0,%1,%2,%3};"
        : "+f"(c[0]), "+f"(c[1]), "+f"(c[2]), "+f"(c[3])
        : "r"(a[0]), "r"(a[1]), "r"(a[2]), "r"(a[3]), "r"(b0), "r"(b1));
}

#define CPA16(dst, src) \
    asm volatile("cp.async.cg.shared.global [%0], [%1], 16;" \
                 :: "r"(dst), "l"(src) : "memory")

// ---------------- W transpose + bf16 hi/lo split ----------------------------
__global__ void wsplit_kernel(const float* __restrict__ W,
                              __nv_bfloat16* __restrict__ hi,
                              __nv_bfloat16* __restrict__ lo, int K) {
    int idx = blockIdx.x * 256 + threadIdx.x;
    if (idx >= K * DH) return;
    int n = idx & (DH - 1), k = idx >> 10;   // W[k][n], row-major (K, 1024)
    float v = W[idx];
    __nv_bfloat16 h = __float2bfloat16(v);
    hi[(size_t)n * K + k] = h;
    lo[(size_t)n * K + k] = __float2bfloat16(v - __bfloat162float(h));
}

// ---------------- tensor-core GEMM via mma.sync (bf16x3 split) --------------
// C[M,1024] = A[M,K] @ W[K,1024]; A fp32 row-major; W pre-split as
// Wt hi/lo bf16 [1024][K] (K-major == col-major B). CTA tile 128x128,
// 8 warps (4m x 2n, 32x64 each), K-chunk 64, 2-stage smem (cp.async for B,
// register prefetch + on-the-fly hi/lo split for A).
// stage layout (64KB): Ahi[16K] Alo[16K] Bhi[16K] Blo[16K]; rows = 128B SW128.
#define GEMM_SMEM (2 * 65536)

__global__ __launch_bounds__(256, 1)
void gemm_mma_kernel(const float* __restrict__ A,
                     const __nv_bfloat16* __restrict__ Bhi,
                     const __nv_bfloat16* __restrict__ Blo,
                     float* __restrict__ C, int M, int K) {
    extern __shared__ __align__(1024) char smem[];
    const int tid = threadIdx.x, wid = tid >> 5, lane = tid & 31;
    const int wm = wid & 3, wn = wid >> 2;
    const int lr = lane & 15, lh = lane >> 4;
    const int row0 = blockIdx.y * 128, col0 = blockIdx.x * 128;
    const uint32_t sb = smem_u32(smem);
    const int nc = K >> 6;

    const int r = tid >> 1, half = tid & 1;
    const int arow = row0 + r;
    const bool aval = (arow < M);
    const float* aptr = A + (size_t)arow * K + half * 32;
    const __nv_bfloat16* bh_g = Bhi + (size_t)(col0 + r) * K + half * 32;
    const __nv_bfloat16* bl_g = Blo + (size_t)(col0 + r) * K + half * 32;
    const uint32_t toff = (uint32_t)(r * 128 + half * 64);

    float4 av[8];
    float acc[2][8][4];
#pragma unroll
    for (int t = 0; t < 2; t++)
#pragma unroll
        for (int j = 0; j < 8; j++)
#pragma unroll
            for (int q = 0; q < 4; q++) acc[t][j][q] = 0.f;

    auto loadA = [&](int c) {
        const float4* p = (const float4*)(aptr + (size_t)c * 64);
        if (aval) {
#pragma unroll
            for (int j = 0; j < 8; j++) av[j] = p[j];
        } else {
#pragma unroll
            for (int j = 0; j < 8; j++) av[j] = make_float4(0.f, 0.f, 0.f, 0.f);
        }
    };

    auto cpaB = [&](int c) {
        uint32_t st = (uint32_t)(c & 1) * 65536;
        const char* ph = (const char*)(bh_g + (size_t)c * 64);
        const char* pl = (const char*)(bl_g + (size_t)c * 64);
#pragma unroll
        for (int q = 0; q < 4; q++) {
            uint32_t c16 = (uint32_t)(half * 4 + q);
            uint32_t d = sb + st + 32768u + (uint32_t)r * 128u +
                         ((c16 ^ (uint32_t)(r & 7)) << 4);
            CPA16(d, ph + q * 16);
            CPA16(d + 16384u, pl + q * 16);
        }
    };

    auto storeA = [&](int c) {
        char* s = smem + (size_t)(c & 1) * 65536;
#pragma unroll
        for (int j = 0; j < 4; j++) {
            float4 f0 = av[2 * j], f1 = av[2 * j + 1];
            __nv_bfloat162 h0 = __floats2bfloat162_rn(f0.x, f0.y);
            __nv_bfloat162 h1 = __floats2bfloat162_rn(f0.z, f0.w);
            __nv_bfloat162 h2 = __floats2bfloat162_rn(f1.x, f1.y);
            __nv_bfloat162 h3 = __floats2bfloat162_rn(f1.z, f1.w);
            __nv_bfloat162 l0 = __floats2bfloat162_rn(f0.x - __bfloat162float(h0.x),
                                                      f0.y - __bfloat162float(h0.y));
            __nv_bfloat162 l1 = __floats2bfloat162_rn(f0.z - __bfloat162float(h1.x),
                                                      f0.w - __bfloat162float(h1.y));
            __nv_bfloat162 l2 = __floats2bfloat162_rn(f1.x - __bfloat162float(h2.x),
                                                      f1.y - __bfloat162float(h2.y));
            __nv_bfloat162 l3 = __floats2bfloat162_rn(f1.z - __bfloat162float(h3.x),
                                                      f1.w - __bfloat162float(h3.y));
            uint4 hv, lv;
            hv.x = *(uint32_t*)&h0; hv.y = *(uint32_t*)&h1;
            hv.z = *(uint32_t*)&h2; hv.w = *(uint32_t*)&h3;
            lv.x = *(uint32_t*)&l0; lv.y = *(uint32_t*)&l1;
            lv.z = *(uint32_t*)&l2; lv.w = *(uint32_t*)&l3;
            uint32_t off = SWZ(toff + (uint32_t)j * 16);
            *(uint4*)(s + off)          = hv;
            *(uint4*)(s + 16384 + off)  = lv;
        }
    };

    auto compute = [&](int c) {
        uint32_t base = sb + (uint32_t)(c & 1) * 65536;
#pragma unroll
        for (int ks = 0; ks < 4; ks++) {
            uint32_t ah[2][4], al[2][4];
#pragma unroll
            for (int t = 0; t < 2; t++) {
                int row = wm * 32 + t * 16 + lr;
                uint32_t c16 = (uint32_t)(ks * 2 + lh);
                uint32_t ad = base + (uint32_t)row * 128u +
                              ((c16 ^ (uint32_t)(row & 7)) << 4);
                ldm4(ah[t], ad);
                ldm4(al[t], ad + 16384u);
            }
            uint32_t bh[4][4], bl[4][4];
#pragma unroll
            for (int g = 0; g < 4; g++) {
                int row = wn * 64 + g * 16 + lr;
                uint32_t c16 = (uint32_t)(ks * 2 + lh);
                uint32_t bd = base + 32768u + (uint32_t)row * 128u +
                              ((c16 ^ (uint32_t)(row & 7)) << 4);
                ldm4(bh[g], bd);
                ldm4(bl[g], bd + 16384u);
            }
#pragma unroll
            for (int t = 0; t < 2; t++)
#pragma unroll
                for (int j = 0; j < 8; j++) {
                    int g = j >> 1, o = j & 1;
                    uint32_t bh0 = bh[g][o], bh1 = bh[g][o + 2];
                    uint32_t bl0 = bl[g][o], bl1 = bl[g][o + 2];
                    mma16816(acc[t][j], ah[t], bh0, bh1);   // hi*hi
                    mma16816(acc[t][j], al[t], bh0, bh1);   // lo*hi
                    mma16816(acc[t][j], ah[t], bl0, bl1);   // hi*lo
                }
        }
    };

    // ---- prologue ----
    cpaB(0);
    asm volatile("cp.async.commit_group;" ::: "memory");
    loadA(0);
    storeA(0);
    if (nc > 1) {
        cpaB(1);
        asm volatile("cp.async.commit_group;" ::: "memory");
        loadA(1);
        asm volatile("cp.async.wait_group 1;" ::: "memory");
    } else {
        asm volatile("cp.async.wait_group 0;" ::: "memory");
    }
    __syncthreads();

    // ---- mainloop ----
    for (int c = 0; c < nc; ++c) {
        compute(c);
        __syncthreads();
        if (c + 1 < nc) {
            storeA(c + 1);                    // av holds A(c+1)
            if (c + 2 < nc) {
                cpaB(c + 2);
                asm volatile("cp.async.commit_group;" ::: "memory");
                loadA(c + 2);
                asm volatile("cp.async.wait_group 1;" ::: "memory");
            } else {
                asm volatile("cp.async.wait_group 0;" ::: "memory");
            }
            __syncthreads();
        }
    }

    // ---- epilogue ----
#pragma unroll
    for (int t = 0; t < 2; t++) {
        int m0 = row0 + wm * 32 + t * 16 + (lane >> 2);
#pragma unroll
        for (int j = 0; j < 8; j++) {
            int col = col0 + wn * 64 + j * 8 + (lane & 3) * 2;
            if (m0 < M)
                *(float2*)(C + (size_t)m0 * DH + col) =
                    make_float2(acc[t][j][0], acc[t][j][1]);
            if (m0 + 8 < M)
                *(float2*)(C + (size_t)(m0 + 8) * DH + col) =
                    make_float2(acc[t][j][2], acc[t][j][3]);
        }
    }
}

// ---------------- attention scores + per-node init --------------------------
__global__ void scores_kernel(const float* __restrict__ h,
                              const float* __restrict__ av,
                              const float* __restrict__ dv,
                              float* __restrict__ es, float* __restrict__ ed,
                              float* __restrict__ m,  float* __restrict__ s) {
    int n = blockIdx.x;
    int w = threadIdx.x >> 5, lane = threadIdx.x & 31;
    const float* hp = h + (size_t)n * DH + w * Cch;
    const float* ap = av + w * Cch;
    const float* bp = dv + w * Cch;
    float s1 = 0.f, s2 = 0.f;
#pragma unroll
    for (int i = 0; i < Cch; i += 32) {
        float v = hp[i + lane];
        s1 = fmaf(v, ap[i + lane], s1);
        s2 = fmaf(v, bp[i + lane], s2);
    }
#pragma unroll
    for (int o = 16; o; o >>= 1) {
        s1 += __shfl_xor_sync(0xffffffffu, s1, o);
        s2 += __shfl_xor_sync(0xffffffffu, s2, o);
    }
    if (lane == 0) {
        es[n * Hh + w] = s1;
        ed[n * Hh + w] = s2;
        m [n * Hh + w] = -INFINITY;
        s [n * Hh + w] = 0.f;
    }
}

// ---------------- edge passes ------------------------------------------------
__global__ void edge_max_kernel(const int* __restrict__ src, const int* __restrict__ dst,
                                const float* __restrict__ es, const float* __restrict__ ed,
                                float* __restrict__ e, float* __restrict__ m) {
    int i = blockIdx.x * blockDim.x + threadIdx.x;
    if (i >= EP) return;
    int s_, d_;
    if (i < Ee) { s_ = src[i]; d_ = dst[i]; } else { s_ = d_ = i - Ee; }
    float4 a = *(const float4*)(es + s_ * 4);
    float4 b = *(const float4*)(ed + d_ * 4);
    float4 ev;
    ev.x = lrelu(a.x + b.x); ev.y = lrelu(a.y + b.y);
    ev.z = lrelu(a.z + b.z); ev.w = lrelu(a.w + b.w);
    *(float4*)(e + (size_t)i * 4) = ev;
    float* mp = m + d_ * 4;
    atomicMaxF(mp + 0, ev.x); atomicMaxF(mp + 1, ev.y);
    atomicMaxF(mp + 2, ev.z); atomicMaxF(mp + 3, ev.w);
}

__global__ void edge_exp_kernel(const int* __restrict__ dst,
                                float* __restrict__ e, const float* __restrict__ m,
                                float* __restrict__ s) {
    int i = blockIdx.x * blockDim.x + threadIdx.x;
    if (i >= EP) return;
    int d_ = (i < Ee) ? dst[i] : (i - Ee);
    float4 ev = *(const float4*)(e + (size_t)i * 4);
    float4 mv = *(const float4*)(m + d_ * 4);
    float4 p;
    p.x = expf(ev.x - mv.x); p.y = expf(ev.y - mv.y);
    p.z = expf(ev.z - mv.z); p.w = expf(ev.w - mv.w);
    *(float4*)(e + (size_t)i * 4) = p;
    redAdd4(s + d_ * 4, p);
}

// one block (256 thr) per edge: acc[dst] += h[src] * alpha
__global__ __launch_bounds__(256)
void scatter_kernel(const int* __restrict__ src, const int* __restrict__ dst,
                    const float* __restrict__ p, const float* __restrict__ ssum,
                    const float* __restrict__ h, float* __restrict__ acc) {
    int e = blockIdx.x;
    int s_, d_;
    if (e < Ee) { s_ = src[e]; d_ = dst[e]; } else { s_ = d_ = e - Ee; }
    __shared__ float al[4];
    if (threadIdx.x < 4)
        al[threadIdx.x] = p[(size_t)e * 4 + threadIdx.x] /
                          (ssum[d_ * 4 + threadIdx.x] + 1e-16f);
    __syncthreads();
    int t = threadIdx.x;
    float a = al[t >> 6];
    float4 v = *(const float4*)(h + (size_t)s_ * DH + t * 4);
    v.x *= a; v.y *= a; v.z *= a; v.w *= a;
    redAdd4(acc + (size_t)d_ * DH + t * 4, v);
}

// ---------------- elementwise ------------------------------------------------
__global__ void fillzero_kernel(float* __restrict__ p, int n4) {
    int i = blockIdx.x * blockDim.x + threadIdx.x;
    if (i < n4) ((float4*)p)[i] = make_float4(0.f, 0.f, 0.f, 0.f);
}

__global__ void finalize_kernel(const float* __restrict__ acc,
                                const float* __restrict__ b,
                                float* __restrict__ out) {
    int i = blockIdx.x * blockDim.x + threadIdx.x;
    if (i >= Nn * DH / 4) return;
    int c4 = (i << 2) & (DH - 1);
    float4 v = ((const float4*)acc)[i];
    float4 bb = *(const float4*)(b + c4);
    v.x = eluf(v.x + bb.x); v.y = eluf(v.y + bb.y);
    v.z = eluf(v.z + bb.z); v.w = eluf(v.w + bb.w);
    ((float4*)out)[i] = v;
}

// ---------------- pooling ----------------------------------------------------
__global__ void pool_init_kernel(float* __restrict__ sum, float* __restrict__ mx,
                                 int* __restrict__ cnt) {
    int i = blockIdx.x * blockDim.x + threadIdx.x;
    if (i < Gg * DH) { sum[i] = 0.f; mx[i] = -INFINITY; }
    if (i < Gg) cnt[i] = 0;
}

__global__ void count_kernel(const int* __restrict__ batch, int* __restrict__ cnt) {
    int i = blockIdx.x * blockDim.x + threadIdx.x;
    if (i < Nn) atomicAdd(&cnt[batch[i]], 1);
}

__global__ void pool_accum_kernel(const float* __restrict__ x, const int* __restrict__ batch,
                                  float* __restrict__ gsum, float* __restrict__ gmax) {
    int c  = blockIdx.x * 256 + threadIdx.x;
    int n0 = blockIdx.y * 128;
    int n1 = min(n0 + 128, Nn);
    float sum = 0.f, mx = -INFINITY;
    int cur = batch[n0];
    for (int n = n0; n < n1; ++n) {
        int g = batch[n];
        if (g != cur) {
            atomicAdd(&gsum[cur * DH + c], sum);
            atomicMaxF(&gmax[cur * DH + c], mx);
            sum = 0.f; mx = -INFINITY; cur = g;
        }
        float v = x[(size_t)n * DH + c];
        sum += v; if (v > mx) mx = v;
    }
    atomicAdd(&gsum[cur * DH + c], sum);
    atomicMaxF(&gmax[cur * DH + c], mx);
}

__global__ void pool_final_kernel(const float* __restrict__ gsum, const float* __restrict__ gmax,
                                  const int* __restrict__ cnt, float* __restrict__ pool) {
    int i = blockIdx.x * blockDim.x + threadIdx.x;
    if (i >= Gg * DH) return;
    int g = i >> 10, c = i & (DH - 1);
    float cf = (float)cnt[g]; if (cf < 1.f) cf = 1.f;
    pool[g * 2 * DH + c] = gsum[i] / cf;
    float mv = gmax[i];
    pool[g * 2 * DH + DH + c] = isfinite(mv) ? mv : 0.f;
}

// ---------------- classifier -------------------------------------------------
__global__ void fc_kernel(const float* __restrict__ in, const float* __restrict__ W,
                          const float* __restrict__ b, float* __restrict__ out,
                          int K, int Nout, int dorelu) {
    __shared__ float sh[2048];
    int g = blockIdx.x;
    for (int k = threadIdx.x; k < K; k += blockDim.x) sh[k] = in[g * K + k];
    __syncthreads();
    int j = threadIdx.x;
    float a = b[j];
#pragma unroll 8
    for (int k = 0; k < K; k++) a = fmaf(sh[k], W[(size_t)k * Nout + j], a);
    if (dorelu) a = fmaxf(a, 0.f);
    out[g * Nout + j] = a;
}

__global__ void fc3_kernel(const float* __restrict__ in, const float* __restrict__ W,
                           const float* __restrict__ b, float* __restrict__ out) {
    int t = threadIdx.x;
    if (t >= Gg * 5) return;
    int g = t / 5, j = t % 5;
    float a = b[j];
    for (int k = 0; k < 256; k++) a = fmaf(in[g * 256 + k], W[k * 5 + j], a);
    out[g * 5 + j] = a;
}

// ---------------- host -------------------------------------------------------
extern "C" void kernel_launch(void* const* d_in, const int* in_sizes, int n_in,
                              void* d_out, int out_size) {
    (void)in_sizes; (void)n_in; (void)out_size;
    const float* x   = (const float*)d_in[0];
    const int*   ei  = (const int*)  d_in[1];
    const int*   bat = (const int*)  d_in[2];
    const float* W1  = (const float*)d_in[3];
    const float* as1 = (const float*)d_in[4];
    const float* ad1 = (const float*)d_in[5];
    const float* b1  = (const float*)d_in[6];
    const float* W2  = (const float*)d_in[7];
    const float* as2 = (const float*)d_in[8];
    const float* ad2 = (const float*)d_in[9];
    const float* b2  = (const float*)d_in[10];
    const float* Wc1 = (const float*)d_in[11];
    const float* bc1 = (const float*)d_in[12];
    const float* Wc2 = (const float*)d_in[13];
    const float* bc2 = (const float*)d_in[14];
    const float* Wc3 = (const float*)d_in[15];
    const float* bc3 = (const float*)d_in[16];
    float* out = (float*)d_out;

    float *ph, *px, *pacc, *pes, *ped, *pm, *ps, *pe, *psum, *pmax, *ppool, *pf1, *pf2;
    int* pcnt;
    __nv_bfloat16 *pwthi, *pwtlo;
    cudaGetSymbolAddress((void**)&ph,   g_h);
    cudaGetSymbolAddress((void**)&px,   g_x);
    cudaGetSymbolAddress((void**)&pacc, g_acc);
    cudaGetSymbolAddress((void**)&pes,  g_esrc);
    cudaGetSymbolAddress((void**)&ped,  g_edst);
    cudaGetSymbolAddress((void**)&pm,   g_m);
    cudaGetSymbolAddress((void**)&ps,   g_s);
    cudaGetSymbolAddress((void**)&pe,   g_e);
    cudaGetSymbolAddress((void**)&psum, g_sum);
    cudaGetSymbolAddress((void**)&pmax, g_max);
    cudaGetSymbolAddress((void**)&pcnt, g_cnt);
    cudaGetSymbolAddress((void**)&ppool,g_pool);
    cudaGetSymbolAddress((void**)&pf1,  g_fc1);
    cudaGetSymbolAddress((void**)&pf2,  g_fc2);
    cudaGetSymbolAddress((void**)&pwthi, g_wthi);
    cudaGetSymbolAddress((void**)&pwtlo, g_wtlo);

    cudaFuncSetAttribute(gemm_mma_kernel,
                         cudaFuncAttributeMaxDynamicSharedMemorySize, GEMM_SMEM);

    const int* src = ei;
    const int* dst = ei + Ee;

    const int N4      = Nn * DH / 4;
    const int GRID_N4 = (N4 + 255) / 256;
    const int GRID_E  = (EP + 255) / 256;
    const dim3 gemm_grid(DH / 128, (Nn + 127) / 128);   // (8, 391)

    // ---- GAT layer 1 ----
    wsplit_kernel<<<(DIN * DH + 255) / 256, 256>>>(W1, pwthi, pwtlo, DIN);
    gemm_mma_kernel<<<gemm_grid, 256, GEMM_SMEM>>>(x, pwthi, pwtlo, ph, Nn, DIN);
    scores_kernel<<<Nn, 128>>>(ph, as1, ad1, pes, ped, pm, ps);
    fillzero_kernel<<<GRID_N4, 256>>>(pacc, N4);
    edge_max_kernel<<<GRID_E, 256>>>(src, dst, pes, ped, pe, pm);
    edge_exp_kernel<<<GRID_E, 256>>>(dst, pe, pm, ps);
    scatter_kernel<<<EP, 256>>>(src, dst, pe, ps, ph, pacc);
    finalize_kernel<<<GRID_N4, 256>>>(pacc, b1, px);

    // ---- GAT layer 2 ----
    wsplit_kernel<<<(DH * DH + 255) / 256, 256>>>(W2, pwthi, pwtlo, DH);
    gemm_mma_kernel<<<gemm_grid, 256, GEMM_SMEM>>>(px, pwthi, pwtlo, ph, Nn, DH);
    scores_kernel<<<Nn, 128>>>(ph, as2, ad2, pes, ped, pm, ps);
    fillzero_kernel<<<GRID_N4, 256>>>(pacc, N4);
    edge_max_kernel<<<GRID_E, 256>>>(src, dst, pes, ped, pe, pm);
    edge_exp_kernel<<<GRID_E, 256>>>(dst, pe, pm, ps);
    scatter_kernel<<<EP, 256>>>(src, dst, pe, ps, ph, pacc);
    finalize_kernel<<<GRID_N4, 256>>>(pacc, b2, px);

    // ---- pooling ----
    pool_init_kernel<<<(Gg * DH + 255) / 256, 256>>>(psum, pmax, pcnt);
    count_kernel<<<(Nn + 255) / 256, 256>>>(bat, pcnt);
    pool_accum_kernel<<<dim3(DH / 256, (Nn + 127) / 128), 256>>>(px, bat, psum, pmax);
    pool_final_kernel<<<(Gg * DH + 255) / 256, 256>>>(psum, pmax, pcnt, ppool);

    // ---- classifier ----
    fc_kernel<<<Gg, 512>>>(ppool, Wc1, bc1, pf1, 2 * DH, 512, 1);
    fc_kernel<<<Gg, 256>>>(pf1, Wc2, bc2, pf2, 512, 256, 1);
    fc3_kernel<<<1, Gg * 5>>>(pf2, Wc3, bc3, out);
}

// round 10
// speedup vs baseline: 1.2122x; 1.2122x over previous
#include <cuda_runtime.h>
#include <cuda_bf16.h>
#include <math.h>
#include <stdint.h>

#define Nn   50000
#define Ee   200000
#define EP   (Ee + Nn)      // 250000 edges incl. self loops
#define Gg   64
#define Hh   4
#define Cch  256
#define DH   1024
#define DIN  768

// ---------------- scratch (device globals; no allocation allowed) ----------
__device__ float g_h  [(size_t)Nn * DH];   // x @ W  (current layer)
__device__ float g_x  [(size_t)Nn * DH];   // layer output (post ELU)
__device__ float g_esrc[Nn * Hh];
__device__ float g_edst[Nn * Hh];
__device__ float g_sum [Gg * DH];
__device__ float g_max [Gg * DH];
__device__ int   g_cnt [Gg];
__device__ float g_pool[Gg * 2 * DH];
__device__ float g_fc1 [Gg * 512];
__device__ float g_fc2 [Gg * 256];
// transposed + hi/lo split weights for tensor-core GEMM: Wt[n][k]
__device__ __nv_bfloat16 g_wthi[(size_t)DH * DH];
__device__ __nv_bfloat16 g_wtlo[(size_t)DH * DH];
// CSR by destination
__device__ int g_deg[Nn];
__device__ int g_off[Nn + 1];
__device__ int g_cur[Nn];
__device__ int g_csr[EP];          // src node per slot

// ---------------- helpers ---------------------------------------------------
__device__ __forceinline__ float lrelu(float x) { return x > 0.f ? x : 0.2f * x; }
__device__ __forceinline__ float eluf (float x) { return x > 0.f ? x : expm1f(x); }

__device__ __forceinline__ void atomicMaxF(float* a, float v) {
    if (v >= 0.f) atomicMax((int*)a, __float_as_int(v));
    else          atomicMin((unsigned int*)a, __float_as_uint(v));
}

__device__ __forceinline__ uint32_t smem_u32(const void* p) {
    uint32_t a;
    asm("{ .reg .u64 t; cvta.to.shared.u64 t, %1; cvt.u32.u64 %0, t; }"
        : "=r"(a) : "l"(p));
    return a;
}

#define SWZ(o) ((o) ^ (((o) >> 3) & 0x70))

__device__ __forceinline__ void ldm4(uint32_t* r, uint32_t addr) {
    asm volatile("ldmatrix.sync.aligned.m8n8.x4.shared.b16 {%0,%1,%2,%3}, [%4];"
                 : "=r"(r[0]), "=r"(r[1]), "=r"(r[2]), "=r"(r[3]) : "r"(addr));
}

__device__ __forceinline__ void mma16816(float* c, const uint32_t* a,
                                         uint32_t b0, uint32_t b1) {
    asm volatile(
        "mma.sync.aligned.m16n8k16.row.col.f32.bf16.bf16.f32 "
        "{%0,%1,%2,%3}, {%4,%5,%6,%7}, {%8,%9}, {%0,%1,%2,%3};"
        : "+f"(c[0]), "+f"(c[1]), "+f"(c[2]), "+f"(c[3])
        : "r"(a[0]), "r"(a[1]), "r"(a[2]), "r"(a[3]), "r"(b0), "r"(b1));
}

#define CPA16(dst, src) \
    asm volatile("cp.async.cg.shared.global [%0], [%1], 16;" \
                 :: "r"(dst), "l"(src) : "memory")

// ---------------- CSR build --------------------------------------------------
__global__ void csr_zero_kernel(int* __restrict__ deg, int* __restrict__ cur) {
    int i = blockIdx.x * 256 + threadIdx.x;
    if (i < Nn) { deg[i] = 0; cur[i] = 0; }
}

__global__ void csr_hist_kernel(const int* __restrict__ dst, int* __restrict__ deg) {
    int i = blockIdx.x * 256 + threadIdx.x;
    if (i >= EP) return;
    int d_ = (i < Ee) ? dst[i] : (i - Ee);
    atomicAdd(&deg[d_], 1);
}

// single block, 1024 threads: exclusive prefix over deg -> off
__global__ void csr_scan_kernel(const int* __restrict__ deg, int* __restrict__ off) {
    __shared__ int bs[1024];
    const int t = threadIdx.x;
    const int per = (Nn + 1023) / 1024;        // 49
    const int b0 = t * per;
    int loc = 0;
    for (int i = 0; i < per; i++) {
        int idx = b0 + i;
        if (idx < Nn) loc += deg[idx];
    }
    bs[t] = loc;
    __syncthreads();
    for (int o = 1; o < 1024; o <<= 1) {
        int v = (t >= o) ? bs[t - o] : 0;
        __syncthreads();
        bs[t] += v;
        __syncthreads();
    }
    int run = t ? bs[t - 1] : 0;
    for (int i = 0; i < per; i++) {
        int idx = b0 + i;
        if (idx < Nn) { off[idx] = run; run += deg[idx]; }
    }
    if (t == 1023) off[Nn] = run;
}

__global__ void csr_fill_kernel(const int* __restrict__ src, const int* __restrict__ dst,
                                const int* __restrict__ off, int* __restrict__ cur,
                                int* __restrict__ csr) {
    int i = blockIdx.x * 256 + threadIdx.x;
    if (i >= EP) return;
    int s_, d_;
    if (i < Ee) { s_ = src[i]; d_ = dst[i]; } else { s_ = d_ = i - Ee; }
    int pos = off[d_] + atomicAdd(&cur[d_], 1);
    csr[pos] = s_;
}

// ---------------- W transpose + bf16 hi/lo split ----------------------------
__global__ void wsplit_kernel(const float* __restrict__ W,
                              __nv_bfloat16* __restrict__ hi,
                              __nv_bfloat16* __restrict__ lo, int K) {
    int idx = blockIdx.x * 256 + threadIdx.x;
    if (idx >= K * DH) return;
    int n = idx & (DH - 1), k = idx >> 10;   // W[k][n], row-major (K, 1024)
    float v = W[idx];
    __nv_bfloat16 h = __float2bfloat16(v);
    hi[(size_t)n * K + k] = h;
    lo[(size_t)n * K + k] = __float2bfloat16(v - __bfloat162float(h));
}

// ---------------- tensor-core GEMM via mma.sync (bf16x3 split) --------------
#define GEMM_SMEM (2 * 65536)

__global__ __launch_bounds__(256, 1)
void gemm_mma_kernel(const float* __restrict__ A,
                     const __nv_bfloat16* __restrict__ Bhi,
                     const __nv_bfloat16* __restrict__ Blo,
                     float* __restrict__ C, int M, int K) {
    extern __shared__ __align__(1024) char smem[];
    const int tid = threadIdx.x, wid = tid >> 5, lane = tid & 31;
    const int wm = wid & 3, wn = wid >> 2;
    const int lr = lane & 15, lh = lane >> 4;
    const int row0 = blockIdx.y * 128, col0 = blockIdx.x * 128;
    const uint32_t sb = smem_u32(smem);
    const int nc = K >> 6;

    const int r = tid >> 1, half = tid & 1;
    const int arow = row0 + r;
    const bool aval = (arow < M);
    const float* aptr = A + (size_t)arow * K + half * 32;
    const __nv_bfloat16* bh_g = Bhi + (size_t)(col0 + r) * K + half * 32;
    const __nv_bfloat16* bl_g = Blo + (size_t)(col0 + r) * K + half * 32;
    const uint32_t toff = (uint32_t)(r * 128 + half * 64);

    float4 av[8];
    float acc[2][8][4];
#pragma unroll
    for (int t = 0; t < 2; t++)
#pragma unroll
        for (int j = 0; j < 8; j++)
#pragma unroll
            for (int q = 0; q < 4; q++) acc[t][j][q] = 0.f;

    auto loadA = [&](int c) {
        const float4* p = (const float4*)(aptr + (size_t)c * 64);
        if (aval) {
#pragma unroll
            for (int j = 0; j < 8; j++) av[j] = p[j];
        } else {
#pragma unroll
            for (int j = 0; j < 8; j++) av[j] = make_float4(0.f, 0.f, 0.f, 0.f);
        }
    };

    auto cpaB = [&](int c) {
        uint32_t st = (uint32_t)(c & 1) * 65536;
        const char* ph = (const char*)(bh_g + (size_t)c * 64);
        const char* pl = (const char*)(bl_g + (size_t)c * 64);
#pragma unroll
        for (int q = 0; q < 4; q++) {
            uint32_t c16 = (uint32_t)(half * 4 + q);
            uint32_t d = sb + st + 32768u + (uint32_t)r * 128u +
                         ((c16 ^ (uint32_t)(r & 7)) << 4);
            CPA16(d, ph + q * 16);
            CPA16(d + 16384u, pl + q * 16);
        }
    };

    auto storeA = [&](int c) {
        char* s = smem + (size_t)(c & 1) * 65536;
#pragma unroll
        for (int j = 0; j < 4; j++) {
            float4 f0 = av[2 * j], f1 = av[2 * j + 1];
            __nv_bfloat162 h0 = __floats2bfloat162_rn(f0.x, f0.y);
            __nv_bfloat162 h1 = __floats2bfloat162_rn(f0.z, f0.w);
            __nv_bfloat162 h2 = __floats2bfloat162_rn(f1.x, f1.y);
            __nv_bfloat162 h3 = __floats2bfloat162_rn(f1.z, f1.w);
            __nv_bfloat162 l0 = __floats2bfloat162_rn(f0.x - __bfloat162float(h0.x),
                                                      f0.y - __bfloat162float(h0.y));
            __nv_bfloat162 l1 = __floats2bfloat162_rn(f0.z - __bfloat162float(h1.x),
                                                      f0.w - __bfloat162float(h1.y));
            __nv_bfloat162 l2 = __floats2bfloat162_rn(f1.x - __bfloat162float(h2.x),
                                                      f1.y - __bfloat162float(h2.y));
            __nv_bfloat162 l3 = __floats2bfloat162_rn(f1.z - __bfloat162float(h3.x),
                                                      f1.w - __bfloat162float(h3.y));
            uint4 hv, lv;
            hv.x = *(uint32_t*)&h0; hv.y = *(uint32_t*)&h1;
            hv.z = *(uint32_t*)&h2; hv.w = *(uint32_t*)&h3;
            lv.x = *(uint32_t*)&l0; lv.y = *(uint32_t*)&l1;
            lv.z = *(uint32_t*)&l2; lv.w = *(uint32_t*)&l3;
            uint32_t off = SWZ(toff + (uint32_t)j * 16);
            *(uint4*)(s + off)          = hv;
            *(uint4*)(s + 16384 + off)  = lv;
        }
    };

    auto compute = [&](int c) {
        uint32_t base = sb + (uint32_t)(c & 1) * 65536;
#pragma unroll
        for (int ks = 0; ks < 4; ks++) {
            uint32_t ah[2][4], al[2][4];
#pragma unroll
            for (int t = 0; t < 2; t++) {
                int row = wm * 32 + t * 16 + lr;
                uint32_t c16 = (uint32_t)(ks * 2 + lh);
                uint32_t ad = base + (uint32_t)row * 128u +
                              ((c16 ^ (uint32_t)(row & 7)) << 4);
                ldm4(ah[t], ad);
                ldm4(al[t], ad + 16384u);
            }
            uint32_t bh[4][4], bl[4][4];
#pragma unroll
            for (int g = 0; g < 4; g++) {
                int row = wn * 64 + g * 16 + lr;
                uint32_t c16 = (uint32_t)(ks * 2 + lh);
                uint32_t bd = base + 32768u + (uint32_t)row * 128u +
                              ((c16 ^ (uint32_t)(row & 7)) << 4);
                ldm4(bh[g], bd);
                ldm4(bl[g], bd + 16384u);
            }
#pragma unroll
            for (int t = 0; t < 2; t++)
#pragma unroll
                for (int j = 0; j < 8; j++) {
                    int g = j >> 1, o = j & 1;
                    uint32_t bh0 = bh[g][o], bh1 = bh[g][o + 2];
                    uint32_t bl0 = bl[g][o], bl1 = bl[g][o + 2];
                    mma16816(acc[t][j], ah[t], bh0, bh1);   // hi*hi
                    mma16816(acc[t][j], al[t], bh0, bh1);   // lo*hi
                    mma16816(acc[t][j], ah[t], bl0, bl1);   // hi*lo
                }
        }
    };

    // ---- prologue ----
    cpaB(0);
    asm volatile("cp.async.commit_group;" ::: "memory");
    loadA(0);
    storeA(0);
    if (nc > 1) {
        cpaB(1);
        asm volatile("cp.async.commit_group;" ::: "memory");
        loadA(1);
        asm volatile("cp.async.wait_group 1;" ::: "memory");
    } else {
        asm volatile("cp.async.wait_group 0;" ::: "memory");
    }
    __syncthreads();

    // ---- mainloop ----
    for (int c = 0; c < nc; ++c) {
        compute(c);
        __syncthreads();
        if (c + 1 < nc) {
            storeA(c + 1);                    // av holds A(c+1)
            if (c + 2 < nc) {
                cpaB(c + 2);
                asm volatile("cp.async.commit_group;" ::: "memory");
                loadA(c + 2);
                asm volatile("cp.async.wait_group 1;" ::: "memory");
            } else {
                asm volatile("cp.async.wait_group 0;" ::: "memory");
            }
            __syncthreads();
        }
    }

    // ---- epilogue ----
#pragma unroll
    for (int t = 0; t < 2; t++) {
        int m0 = row0 + wm * 32 + t * 16 + (lane >> 2);
#pragma unroll
        for (int j = 0; j < 8; j++) {
            int col = col0 + wn * 64 + j * 8 + (lane & 3) * 2;
            if (m0 < M)
                *(float2*)(C + (size_t)m0 * DH + col) =
                    make_float2(acc[t][j][0], acc[t][j][1]);
            if (m0 + 8 < M)
                *(float2*)(C + (size_t)(m0 + 8) * DH + col) =
                    make_float2(acc[t][j][2], acc[t][j][3]);
        }
    }
}

// ---------------- attention scores -------------------------------------------
__global__ void scores_kernel(const float* __restrict__ h,
                              const float* __restrict__ av,
                              const float* __restrict__ dv,
                              float* __restrict__ es, float* __restrict__ ed) {
    int n = blockIdx.x;
    int w = threadIdx.x >> 5, lane = threadIdx.x & 31;
    const float* hp = h + (size_t)n * DH + w * Cch;
    const float* ap = av + w * Cch;
    const float* bp = dv + w * Cch;
    float s1 = 0.f, s2 = 0.f;
#pragma unroll
    for (int i = 0; i < Cch; i += 32) {
        float v = hp[i + lane];
        s1 = fmaf(v, ap[i + lane], s1);
        s2 = fmaf(v, bp[i + lane], s2);
    }
#pragma unroll
    for (int o = 16; o; o >>= 1) {
        s1 += __shfl_xor_sync(0xffffffffu, s1, o);
        s2 += __shfl_xor_sync(0xffffffffu, s2, o);
    }
    if (lane == 0) {
        es[n * Hh + w] = s1;
        ed[n * Hh + w] = s2;
    }
}

// ---------------- fused softmax + gather aggregation -------------------------
// one 256-thread block per destination node. Warp w (0..3) computes head-w
// softmax stats over incoming edges; then all threads gather h[src] rows in
// chunks of 64 edges with alphas staged in smem; bias + ELU fused at the end.
__global__ __launch_bounds__(256)
void agg_kernel(const int* __restrict__ off, const int* __restrict__ csr,
                const float* __restrict__ es, const float* __restrict__ ed,
                const float* __restrict__ h, const float* __restrict__ bias,
                float* __restrict__ out) {
    const int d = blockIdx.x;
    const int beg = off[d], end = off[d + 1];
    const int deg = end - beg;
    const int tid = threadIdx.x, wid = tid >> 5, lane = tid & 31;

    __shared__ float sm[4], ss[4];
    __shared__ float al[4][64];

    if (wid < 4) {
        const float edv = ed[d * 4 + wid];
        float mx = -INFINITY;
        for (int i = beg + lane; i < end; i += 32) {
            int s_ = csr[i];
            mx = fmaxf(mx, lrelu(es[s_ * 4 + wid] + edv));
        }
#pragma unroll
        for (int o = 16; o; o >>= 1)
            mx = fmaxf(mx, __shfl_xor_sync(0xffffffffu, mx, o));
        float su = 0.f;
        for (int i = beg + lane; i < end; i += 32) {
            int s_ = csr[i];
            su += expf(lrelu(es[s_ * 4 + wid] + edv) - mx);
        }
#pragma unroll
        for (int o = 16; o; o >>= 1)
            su += __shfl_xor_sync(0xffffffffu, su, o);
        if (lane == 0) { sm[wid] = mx; ss[wid] = su; }
    }
    __syncthreads();

    const int head = tid >> 6;              // col = tid*4, head = col/256
    float4 acc = make_float4(0.f, 0.f, 0.f, 0.f);

    for (int c0 = 0; c0 < deg; c0 += 64) {
        {   // stage alphas for this chunk: thread t -> (head t>>6, edge t&63)
            int j = tid & 63, hh = tid >> 6;
            if (c0 + j < deg) {
                int s_ = csr[beg + c0 + j];
                float e = lrelu(es[s_ * 4 + hh] + ed[d * 4 + hh]);
                al[hh][j] = expf(e - sm[hh]) / (ss[hh] + 1e-16f);
            }
        }
        __syncthreads();
        int lim = min(64, deg - c0);
        for (int j = 0; j < lim; j++) {
            int s_ = csr[beg + c0 + j];
            float a = al[head][j];
            float4 v = *(const float4*)(h + (size_t)s_ * DH + tid * 4);
            acc.x = fmaf(a, v.x, acc.x);
            acc.y = fmaf(a, v.y, acc.y);
            acc.z = fmaf(a, v.z, acc.z);
            acc.w = fmaf(a, v.w, acc.w);
        }
        __syncthreads();
    }

    float4 bb = *(const float4*)(bias + tid * 4);
    acc.x = eluf(acc.x + bb.x);
    acc.y = eluf(acc.y + bb.y);
    acc.z = eluf(acc.z + bb.z);
    acc.w = eluf(acc.w + bb.w);
    *(float4*)(out + (size_t)d * DH + tid * 4) = acc;
}

// ---------------- pooling ----------------------------------------------------
__global__ void pool_init_kernel(float* __restrict__ sum, float* __restrict__ mx,
                                 int* __restrict__ cnt) {
    int i = blockIdx.x * blockDim.x + threadIdx.x;
    if (i < Gg * DH) { sum[i] = 0.f; mx[i] = -INFINITY; }
    if (i < Gg) cnt[i] = 0;
}

__global__ void count_kernel(const int* __restrict__ batch, int* __restrict__ cnt) {
    int i = blockIdx.x * blockDim.x + threadIdx.x;
    if (i < Nn) atomicAdd(&cnt[batch[i]], 1);
}

__global__ void pool_accum_kernel(const float* __restrict__ x, const int* __restrict__ batch,
                                  float* __restrict__ gsum, float* __restrict__ gmax) {
    int c  = blockIdx.x * 256 + threadIdx.x;
    int n0 = blockIdx.y * 128;
    int n1 = min(n0 + 128, Nn);
    float sum = 0.f, mx = -INFINITY;
    int cur = batch[n0];
    for (int n = n0; n < n1; ++n) {
        int g = batch[n];
        if (g != cur) {
            atomicAdd(&gsum[cur * DH + c], sum);
            atomicMaxF(&gmax[cur * DH + c], mx);
            sum = 0.f; mx = -INFINITY; cur = g;
        }
        float v = x[(size_t)n * DH + c];
        sum += v; if (v > mx) mx = v;
    }
    atomicAdd(&gsum[cur * DH + c], sum);
    atomicMaxF(&gmax[cur * DH + c], mx);
}

__global__ void pool_final_kernel(const float* __restrict__ gsum, const float* __restrict__ gmax,
                                  const int* __restrict__ cnt, float* __restrict__ pool) {
    int i = blockIdx.x * blockDim.x + threadIdx.x;
    if (i >= Gg * DH) return;
    int g = i >> 10, c = i & (DH - 1);
    float cf = (float)cnt[g]; if (cf < 1.f) cf = 1.f;
    pool[g * 2 * DH + c] = gsum[i] / cf;
    float mv = gmax[i];
    pool[g * 2 * DH + DH + c] = isfinite(mv) ? mv : 0.f;
}

// ---------------- classifier -------------------------------------------------
__global__ void fc_kernel(const float* __restrict__ in, const float* __restrict__ W,
                          const float* __restrict__ b, float* __restrict__ out,
                          int K, int Nout, int dorelu) {
    __shared__ float sh[2048];
    int g = blockIdx.x;
    for (int k = threadIdx.x; k < K; k += blockDim.x) sh[k] = in[g * K + k];
    __syncthreads();
    int j = threadIdx.x;
    float a = b[j];
#pragma unroll 8
    for (int k = 0; k < K; k++) a = fmaf(sh[k], W[(size_t)k * Nout + j], a);
    if (dorelu) a = fmaxf(a, 0.f);
    out[g * Nout + j] = a;
}

__global__ void fc3_kernel(const float* __restrict__ in, const float* __restrict__ W,
                           const float* __restrict__ b, float* __restrict__ out) {
    int t = threadIdx.x;
    if (t >= Gg * 5) return;
    int g = t / 5, j = t % 5;
    float a = b[j];
    for (int k = 0; k < 256; k++) a = fmaf(in[g * 256 + k], W[k * 5 + j], a);
    out[g * 5 + j] = a;
}

// ---------------- host -------------------------------------------------------
extern "C" void kernel_launch(void* const* d_in, const int* in_sizes, int n_in,
                              void* d_out, int out_size) {
    (void)in_sizes; (void)n_in; (void)out_size;
    const float* x   = (const float*)d_in[0];
    const int*   ei  = (const int*)  d_in[1];
    const int*   bat = (const int*)  d_in[2];
    const float* W1  = (const float*)d_in[3];
    const float* as1 = (const float*)d_in[4];
    const float* ad1 = (const float*)d_in[5];
    const float* b1  = (const float*)d_in[6];
    const float* W2  = (const float*)d_in[7];
    const float* as2 = (const float*)d_in[8];
    const float* ad2 = (const float*)d_in[9];
    const float* b2  = (const float*)d_in[10];
    const float* Wc1 = (const float*)d_in[11];
    const float* bc1 = (const float*)d_in[12];
    const float* Wc2 = (const float*)d_in[13];
    const float* bc2 = (const float*)d_in[14];
    const float* Wc3 = (const float*)d_in[15];
    const float* bc3 = (const float*)d_in[16];
    float* out = (float*)d_out;

    float *ph, *px, *pes, *ped, *psum, *pmax, *ppool, *pf1, *pf2;
    int *pcnt, *pdeg, *poff, *pcur, *pcsr;
    __nv_bfloat16 *pwthi, *pwtlo;
    cudaGetSymbolAddress((void**)&ph,   g_h);
    cudaGetSymbolAddress((void**)&px,   g_x);
    cudaGetSymbolAddress((void**)&pes,  g_esrc);
    cudaGetSymbolAddress((void**)&ped,  g_edst);
    cudaGetSymbolAddress((void**)&psum, g_sum);
    cudaGetSymbolAddress((void**)&pmax, g_max);
    cudaGetSymbolAddress((void**)&pcnt, g_cnt);
    cudaGetSymbolAddress((void**)&ppool,g_pool);
    cudaGetSymbolAddress((void**)&pf1,  g_fc1);
    cudaGetSymbolAddress((void**)&pf2,  g_fc2);
    cudaGetSymbolAddress((void**)&pwthi, g_wthi);
    cudaGetSymbolAddress((void**)&pwtlo, g_wtlo);
    cudaGetSymbolAddress((void**)&pdeg, g_deg);
    cudaGetSymbolAddress((void**)&poff, g_off);
    cudaGetSymbolAddress((void**)&pcur, g_cur);
    cudaGetSymbolAddress((void**)&pcsr, g_csr);

    cudaFuncSetAttribute(gemm_mma_kernel,
                         cudaFuncAttributeMaxDynamicSharedMemorySize, GEMM_SMEM);

    const int* src = ei;
    const int* dst = ei + Ee;

    const int GRID_E = (EP + 255) / 256;
    const int GRID_N = (Nn + 255) / 256;
    const dim3 gemm_grid(DH / 128, (Nn + 127) / 128);   // (8, 391)

    // ---- CSR build (graph is identical for both layers) ----
    csr_zero_kernel<<<GRID_N, 256>>>(pdeg, pcur);
    csr_hist_kernel<<<GRID_E, 256>>>(dst, pdeg);
    csr_scan_kernel<<<1, 1024>>>(pdeg, poff);
    csr_fill_kernel<<<GRID_E, 256>>>(src, dst, poff, pcur, pcsr);

    // ---- GAT layer 1 ----
    wsplit_kernel<<<(DIN * DH + 255) / 256, 256>>>(W1, pwthi, pwtlo, DIN);
    gemm_mma_kernel<<<gemm_grid, 256, GEMM_SMEM>>>(x, pwthi, pwtlo, ph, Nn, DIN);
    scores_kernel<<<Nn, 128>>>(ph, as1, ad1, pes, ped);
    agg_kernel<<<Nn, 256>>>(poff, pcsr, pes, ped, ph, b1, px);

    // ---- GAT layer 2 ----
    wsplit_kernel<<<(DH * DH + 255) / 256, 256>>>(W2, pwthi, pwtlo, DH);
    gemm_mma_kernel<<<gemm_grid, 256, GEMM_SMEM>>>(px, pwthi, pwtlo, ph, Nn, DH);
    scores_kernel<<<Nn, 128>>>(ph, as2, ad2, pes, ped);
    agg_kernel<<<Nn, 256>>>(poff, pcsr, pes, ped, ph, b2, px);

    // ---- pooling ----
    pool_init_kernel<<<(Gg * DH + 255) / 256, 256>>>(psum, pmax, pcnt);
    count_kernel<<<GRID_N, 256>>>(bat, pcnt);
    pool_accum_kernel<<<dim3(DH / 256, (Nn + 127) / 128), 256>>>(px, bat, psum, pmax);
    pool_final_kernel<<<(Gg * DH + 255) / 256, 256>>>(psum, pmax, pcnt, ppool);

    // ---- classifier ----
    fc_kernel<<<Gg, 512>>>(ppool, Wc1, bc1, pf1, 2 * DH, 512, 1);
    fc_kernel<<<Gg, 256>>>(pf1, Wc2, bc2, pf2, 512, 256, 1);
    fc3_kernel<<<1, Gg * 5>>>(pf2, Wc3, bc3, out);
}

// round 11
// speedup vs baseline: 1.4338x; 1.1828x over previous
#include <cuda_runtime.h>
#include <cuda_bf16.h>
#include <math.h>
#include <stdint.h>

#define Nn   50000
#define Ee   200000
#define EP   (Ee + Nn)      // 250000 edges incl. self loops
#define Gg   64
#define Hh   4
#define Cch  256
#define DH   1024
#define DIN  768

// ---------------- scratch (device globals; no allocation allowed) ----------
__device__ float g_h  [(size_t)Nn * DH];   // x @ W  (current layer)
__device__ float g_x  [(size_t)Nn * DH];   // layer output (post ELU)
__device__ float g_esrc[Nn * Hh];
__device__ float g_edst[Nn * Hh];
__device__ float g_sum [Gg * DH];
__device__ float g_max [Gg * DH];
__device__ int   g_cnt [Gg];
__device__ float g_pool[Gg * 2 * DH];
__device__ float g_fc1 [Gg * 512];
__device__ float g_fc2 [Gg * 256];
// transposed + hi/lo split weights: Wt[n][k]
__device__ __nv_bfloat16 g_wthi[(size_t)DH * DH];
__device__ __nv_bfloat16 g_wtlo[(size_t)DH * DH];
// hi/lo split activations (GEMM A operand)
__device__ __nv_bfloat16 g_ahi[(size_t)Nn * DH];
__device__ __nv_bfloat16 g_alo[(size_t)Nn * DH];
// CSR by destination
__device__ int g_deg[Nn];
__device__ int g_off[Nn + 1];
__device__ int g_cur[Nn];
__device__ int g_csr[EP];          // src node per slot

// ---------------- helpers ---------------------------------------------------
__device__ __forceinline__ float lrelu(float x) { return x > 0.f ? x : 0.2f * x; }
__device__ __forceinline__ float eluf (float x) { return x > 0.f ? x : expm1f(x); }

__device__ __forceinline__ void atomicMaxF(float* a, float v) {
    if (v >= 0.f) atomicMax((int*)a, __float_as_int(v));
    else          atomicMin((unsigned int*)a, __float_as_uint(v));
}

__device__ __forceinline__ uint32_t smem_u32(const void* p) {
    uint32_t a;
    asm("{ .reg .u64 t; cvta.to.shared.u64 t, %1; cvt.u32.u64 %0, t; }"
        : "=r"(a) : "l"(p));
    return a;
}

__device__ __forceinline__ void ldm4(uint32_t* r, uint32_t addr) {
    asm volatile("ldmatrix.sync.aligned.m8n8.x4.shared.b16 {%0,%1,%2,%3}, [%4];"
                 : "=r"(r[0]), "=r"(r[1]), "=r"(r[2]), "=r"(r[3]) : "r"(addr));
}

__device__ __forceinline__ void mma16816(float* c, const uint32_t* a,
                                         uint32_t b0, uint32_t b1) {
    asm volatile(
        "mma.sync.aligned.m16n8k16.row.col.f32.bf16.bf16.f32 "
        "{%0,%1,%2,%3}, {%4,%5,%6,%7}, {%8,%9}, {%0,%1,%2,%3};"
        : "+f"(c[0]), "+f"(c[1]), "+f"(c[2]), "+f"(c[3])
        : "r"(a[0]), "r"(a[1]), "r"(a[2]), "r"(a[3]), "r"(b0), "r"(b1));
}

#define CPA16(dst, src) \
    asm volatile("cp.async.cg.shared.global [%0], [%1], 16;" \
                 :: "r"(dst), "l"(src) : "memory")
#define CPA16Z(dst, src, szr) \
    asm volatile("cp.async.cg.shared.global [%0], [%1], 16, %2;" \
                 :: "r"(dst), "l"(src), "r"(szr) : "memory")

// ---------------- CSR build --------------------------------------------------
__global__ void csr_zero_kernel(int* __restrict__ deg, int* __restrict__ cur) {
    int i = blockIdx.x * 256 + threadIdx.x;
    if (i < Nn) { deg[i] = 0; cur[i] = 0; }
}

__global__ void csr_hist_kernel(const int* __restrict__ dst, int* __restrict__ deg) {
    int i = blockIdx.x * 256 + threadIdx.x;
    if (i >= EP) return;
    int d_ = (i < Ee) ? dst[i] : (i - Ee);
    atomicAdd(&deg[d_], 1);
}

__global__ void csr_scan_kernel(const int* __restrict__ deg, int* __restrict__ off) {
    __shared__ int bs[1024];
    const int t = threadIdx.x;
    const int per = (Nn + 1023) / 1024;        // 49
    const int b0 = t * per;
    int loc = 0;
    for (int i = 0; i < per; i++) {
        int idx = b0 + i;
        if (idx < Nn) loc += deg[idx];
    }
    bs[t] = loc;
    __syncthreads();
    for (int o = 1; o < 1024; o <<= 1) {
        int v = (t >= o) ? bs[t - o] : 0;
        __syncthreads();
        bs[t] += v;
        __syncthreads();
    }
    int run = t ? bs[t - 1] : 0;
    for (int i = 0; i < per; i++) {
        int idx = b0 + i;
        if (idx < Nn) { off[idx] = run; run += deg[idx]; }
    }
    if (t == 1023) off[Nn] = run;
}

__global__ void csr_fill_kernel(const int* __restrict__ src, const int* __restrict__ dst,
                                const int* __restrict__ off, int* __restrict__ cur,
                                int* __restrict__ csr) {
    int i = blockIdx.x * 256 + threadIdx.x;
    if (i >= EP) return;
    int s_, d_;
    if (i < Ee) { s_ = src[i]; d_ = dst[i]; } else { s_ = d_ = i - Ee; }
    int pos = off[d_] + atomicAdd(&cur[d_], 1);
    csr[pos] = s_;
}

// ---------------- splits -----------------------------------------------------
__global__ void wsplit_kernel(const float* __restrict__ W,
                              __nv_bfloat16* __restrict__ hi,
                              __nv_bfloat16* __restrict__ lo, int K) {
    int idx = blockIdx.x * 256 + threadIdx.x;
    if (idx >= K * DH) return;
    int n = idx & (DH - 1), k = idx >> 10;   // W[k][n], row-major (K, 1024)
    float v = W[idx];
    __nv_bfloat16 h = __float2bfloat16(v);
    hi[(size_t)n * K + k] = h;
    lo[(size_t)n * K + k] = __float2bfloat16(v - __bfloat162float(h));
}

__global__ void asplit_kernel(const float* __restrict__ A,
                              __nv_bfloat16* __restrict__ hi,
                              __nv_bfloat16* __restrict__ lo, int total) {
    int idx = blockIdx.x * 256 + threadIdx.x;
    if (idx >= total) return;
    float v = A[idx];
    __nv_bfloat16 h = __float2bfloat16(v);
    hi[idx] = h;
    lo[idx] = __float2bfloat16(v - __bfloat162float(h));
}

// ---------------- tensor-core GEMM via mma.sync (bf16x3 split) --------------
// C[M,1024] = A[M,K] @ W[K,1024]; A pre-split hi/lo bf16 row-major [M][K];
// W pre-split hi/lo bf16 K-major [1024][K]. CTA tile 128x256, 512 threads,
// 16 warps (4m x 4n, 32x64 each), K-chunk 64, 2-stage cp.async pipeline.
// stage (96KB): Ahi[16K] Alo[16K] Bhi[32K] Blo[32K]; 128B SW128 rows.
#define GEMM_SMEM (2 * 98304)

__global__ __launch_bounds__(512, 1)
void gemm_mma_kernel(const __nv_bfloat16* __restrict__ Ahi,
                     const __nv_bfloat16* __restrict__ Alo,
                     const __nv_bfloat16* __restrict__ Bhi,
                     const __nv_bfloat16* __restrict__ Blo,
                     float* __restrict__ C, int M, int K) {
    extern __shared__ __align__(1024) char smem[];
    const int tid = threadIdx.x, wid = tid >> 5, lane = tid & 31;
    const int wm = wid & 3, wn = wid >> 2;
    const int lr = lane & 15, lh = lane >> 4;
    const int row0 = blockIdx.y * 128, col0 = blockIdx.x * 256;
    const uint32_t sb = smem_u32(smem);
    const int nc = K >> 6;

    float acc[2][8][4];
#pragma unroll
    for (int t = 0; t < 2; t++)
#pragma unroll
        for (int j = 0; j < 8; j++)
#pragma unroll
            for (int q = 0; q < 4; q++) acc[t][j][q] = 0.f;

    auto loadStage = [&](int ck) {
        uint32_t st = sb + (uint32_t)(ck & 1) * 98304u;
        const __nv_bfloat16* Ah = Ahi + (size_t)row0 * K + ck * 64;
        const __nv_bfloat16* Al = Alo + (size_t)row0 * K + ck * 64;
#pragma unroll
        for (int u = tid; u < 1024; u += 512) {
            int r = u >> 3, c = u & 7;
            uint32_t d = st + (uint32_t)(r * 128) + (uint32_t)((c ^ (r & 7)) << 4);
            uint32_t sz = (row0 + r < M) ? 16u : 0u;
            CPA16Z(d,          Ah + (size_t)r * K + c * 8, sz);
            CPA16Z(d + 16384u, Al + (size_t)r * K + c * 8, sz);
        }
        const __nv_bfloat16* Bh = Bhi + (size_t)col0 * K + ck * 64;
        const __nv_bfloat16* Bl = Blo + (size_t)col0 * K + ck * 64;
#pragma unroll
        for (int u = tid; u < 2048; u += 512) {
            int r = u >> 3, c = u & 7;
            uint32_t d = st + 32768u + (uint32_t)(r * 128) +
                         (uint32_t)((c ^ (r & 7)) << 4);
            CPA16(d,          Bh + (size_t)r * K + c * 8);
            CPA16(d + 32768u, Bl + (size_t)r * K + c * 8);
        }
        asm volatile("cp.async.commit_group;" ::: "memory");
    };

    auto compute = [&](int ck) {
        uint32_t base = sb + (uint32_t)(ck & 1) * 98304u;
#pragma unroll
        for (int ks = 0; ks < 4; ks++) {
            uint32_t c16 = (uint32_t)(ks * 2 + lh);
            uint32_t ah[2][4], al[2][4];
#pragma unroll
            for (int t = 0; t < 2; t++) {
                int row = wm * 32 + t * 16 + lr;
                uint32_t ad = base + (uint32_t)(row * 128) +
                              ((c16 ^ (uint32_t)(row & 7)) << 4);
                ldm4(ah[t], ad);
                ldm4(al[t], ad + 16384u);
            }
#pragma unroll
            for (int g = 0; g < 4; g++) {
                int row = wn * 64 + g * 16 + lr;
                uint32_t bd = base + 32768u + (uint32_t)(row * 128) +
                              ((c16 ^ (uint32_t)(row & 7)) << 4);
                uint32_t bh[4], bl[4];
                ldm4(bh, bd);
                ldm4(bl, bd + 32768u);
#pragma unroll
                for (int t = 0; t < 2; t++)
#pragma unroll
                    for (int o = 0; o < 2; o++) {
                        float* a4 = acc[t][g * 2 + o];
                        mma16816(a4, ah[t], bh[o], bh[o + 2]);   // hi*hi
                        mma16816(a4, al[t], bh[o], bh[o + 2]);   // lo*hi
                        mma16816(a4, ah[t], bl[o], bl[o + 2]);   // hi*lo
                    }
            }
        }
    };

    // ---- prologue ----
    loadStage(0);
    if (nc > 1) loadStage(1);
    asm volatile("cp.async.wait_group %0;" :: "n"(1) : "memory");
    __syncthreads();

    // ---- mainloop ----
    for (int c = 0; c < nc; ++c) {
        compute(c);
        __syncthreads();
        if (c + 1 < nc) {
            if (c + 2 < nc) {
                loadStage(c + 2);
                asm volatile("cp.async.wait_group %0;" :: "n"(1) : "memory");
            } else {
                asm volatile("cp.async.wait_group %0;" :: "n"(0) : "memory");
            }
            __syncthreads();
        }
    }

    // ---- epilogue ----
#pragma unroll
    for (int t = 0; t < 2; t++) {
        int m0 = row0 + wm * 32 + t * 16 + (lane >> 2);
#pragma unroll
        for (int j = 0; j < 8; j++) {
            int col = col0 + wn * 64 + j * 8 + (lane & 3) * 2;
            if (m0 < M)
                *(float2*)(C + (size_t)m0 * DH + col) =
                    make_float2(acc[t][j][0], acc[t][j][1]);
            if (m0 + 8 < M)
                *(float2*)(C + (size_t)(m0 + 8) * DH + col) =
                    make_float2(acc[t][j][2], acc[t][j][3]);
        }
    }
}

// ---------------- attention scores -------------------------------------------
__global__ void scores_kernel(const float* __restrict__ h,
                              const float* __restrict__ av,
                              const float* __restrict__ dv,
                              float* __restrict__ es, float* __restrict__ ed) {
    int n = blockIdx.x;
    int w = threadIdx.x >> 5, lane = threadIdx.x & 31;
    const float* hp = h + (size_t)n * DH + w * Cch;
    const float* ap = av + w * Cch;
    const float* bp = dv + w * Cch;
    float s1 = 0.f, s2 = 0.f;
#pragma unroll
    for (int i = 0; i < Cch; i += 32) {
        float v = hp[i + lane];
        s1 = fmaf(v, ap[i + lane], s1);
        s2 = fmaf(v, bp[i + lane], s2);
    }
#pragma unroll
    for (int o = 16; o; o >>= 1) {
        s1 += __shfl_xor_sync(0xffffffffu, s1, o);
        s2 += __shfl_xor_sync(0xffffffffu, s2, o);
    }
    if (lane == 0) {
        es[n * Hh + w] = s1;
        ed[n * Hh + w] = s2;
    }
}

// ---------------- fused softmax + gather aggregation -------------------------
// one 256-thread block per destination node; optionally also emits the bf16
// hi/lo split of the ELU output (consumed by the next layer's GEMM).
__global__ __launch_bounds__(256)
void agg_kernel(const int* __restrict__ off, const int* __restrict__ csr,
                const float* __restrict__ es, const float* __restrict__ ed,
                const float* __restrict__ h, const float* __restrict__ bias,
                float* __restrict__ out,
                __nv_bfloat16* __restrict__ ohi, __nv_bfloat16* __restrict__ olo) {
    const int d = blockIdx.x;
    const int beg = off[d], end = off[d + 1];
    const int deg = end - beg;
    const int tid = threadIdx.x, wid = tid >> 5, lane = tid & 31;

    __shared__ float sm[4], ss[4];
    __shared__ float al[4][64];

    if (wid < 4) {
        const float edv = ed[d * 4 + wid];
        float mx = -INFINITY;
        for (int i = beg + lane; i < end; i += 32) {
            int s_ = csr[i];
            mx = fmaxf(mx, lrelu(es[s_ * 4 + wid] + edv));
        }
#pragma unroll
        for (int o = 16; o; o >>= 1)
            mx = fmaxf(mx, __shfl_xor_sync(0xffffffffu, mx, o));
        float su = 0.f;
        for (int i = beg + lane; i < end; i += 32) {
            int s_ = csr[i];
            su += expf(lrelu(es[s_ * 4 + wid] + edv) - mx);
        }
#pragma unroll
        for (int o = 16; o; o >>= 1)
            su += __shfl_xor_sync(0xffffffffu, su, o);
        if (lane == 0) { sm[wid] = mx; ss[wid] = su; }
    }
    __syncthreads();

    const int head = tid >> 6;
    float4 acc = make_float4(0.f, 0.f, 0.f, 0.f);

    for (int c0 = 0; c0 < deg; c0 += 64) {
        {
            int j = tid & 63, hh = tid >> 6;
            if (c0 + j < deg) {
                int s_ = csr[beg + c0 + j];
                float e = lrelu(es[s_ * 4 + hh] + ed[d * 4 + hh]);
                al[hh][j] = expf(e - sm[hh]) / (ss[hh] + 1e-16f);
            }
        }
        __syncthreads();
        int lim = min(64, deg - c0);
        for (int j = 0; j < lim; j++) {
            int s_ = csr[beg + c0 + j];
            float a = al[head][j];
            float4 v = *(const float4*)(h + (size_t)s_ * DH + tid * 4);
            acc.x = fmaf(a, v.x, acc.x);
            acc.y = fmaf(a, v.y, acc.y);
            acc.z = fmaf(a, v.z, acc.z);
            acc.w = fmaf(a, v.w, acc.w);
        }
        __syncthreads();
    }

    float4 bb = *(const float4*)(bias + tid * 4);
    acc.x = eluf(acc.x + bb.x);
    acc.y = eluf(acc.y + bb.y);
    acc.z = eluf(acc.z + bb.z);
    acc.w = eluf(acc.w + bb.w);
    *(float4*)(out + (size_t)d * DH + tid * 4) = acc;

    if (ohi) {
        __nv_bfloat162 h0 = __floats2bfloat162_rn(acc.x, acc.y);
        __nv_bfloat162 h1 = __floats2bfloat162_rn(acc.z, acc.w);
        __nv_bfloat162 l0 = __floats2bfloat162_rn(acc.x - __bfloat162float(h0.x),
                                                  acc.y - __bfloat162float(h0.y));
        __nv_bfloat162 l1 = __floats2bfloat162_rn(acc.z - __bfloat162float(h1.x),
                                                  acc.w - __bfloat162float(h1.y));
        *(__nv_bfloat162*)(ohi + (size_t)d * DH + tid * 4)     = h0;
        *(__nv_bfloat162*)(ohi + (size_t)d * DH + tid * 4 + 2) = h1;
        *(__nv_bfloat162*)(olo + (size_t)d * DH + tid * 4)     = l0;
        *(__nv_bfloat162*)(olo + (size_t)d * DH + tid * 4 + 2) = l1;
    }
}

// ---------------- pooling ----------------------------------------------------
__global__ void pool_init_kernel(float* __restrict__ sum, float* __restrict__ mx,
                                 int* __restrict__ cnt) {
    int i = blockIdx.x * blockDim.x + threadIdx.x;
    if (i < Gg * DH) { sum[i] = 0.f; mx[i] = -INFINITY; }
    if (i < Gg) cnt[i] = 0;
}

__global__ void count_kernel(const int* __restrict__ batch, int* __restrict__ cnt) {
    int i = blockIdx.x * blockDim.x + threadIdx.x;
    if (i < Nn) atomicAdd(&cnt[batch[i]], 1);
}

__global__ void pool_accum_kernel(const float* __restrict__ x, const int* __restrict__ batch,
                                  float* __restrict__ gsum, float* __restrict__ gmax) {
    int c  = blockIdx.x * 256 + threadIdx.x;
    int n0 = blockIdx.y * 128;
    int n1 = min(n0 + 128, Nn);
    float sum = 0.f, mx = -INFINITY;
    int cur = batch[n0];
    for (int n = n0; n < n1; ++n) {
        int g = batch[n];
        if (g != cur) {
            atomicAdd(&gsum[cur * DH + c], sum);
            atomicMaxF(&gmax[cur * DH + c], mx);
            sum = 0.f; mx = -INFINITY; cur = g;
        }
        float v = x[(size_t)n * DH + c];
        sum += v; if (v > mx) mx = v;
    }
    atomicAdd(&gsum[cur * DH + c], sum);
    atomicMaxF(&gmax[cur * DH + c], mx);
}

__global__ void pool_final_kernel(const float* __restrict__ gsum, const float* __restrict__ gmax,
                                  const int* __restrict__ cnt, float* __restrict__ pool) {
    int i = blockIdx.x * blockDim.x + threadIdx.x;
    if (i >= Gg * DH) return;
    int g = i >> 10, c = i & (DH - 1);
    float cf = (float)cnt[g]; if (cf < 1.f) cf = 1.f;
    pool[g * 2 * DH + c] = gsum[i] / cf;
    float mv = gmax[i];
    pool[g * 2 * DH + DH + c] = isfinite(mv) ? mv : 0.f;
}

// ---------------- classifier -------------------------------------------------
__global__ void fc_kernel(const float* __restrict__ in, const float* __restrict__ W,
                          const float* __restrict__ b, float* __restrict__ out,
                          int K, int Nout, int dorelu) {
    __shared__ float sh[2048];
    int g = blockIdx.x;
    for (int k = threadIdx.x; k < K; k += blockDim.x) sh[k] = in[g * K + k];
    __syncthreads();
    int j = threadIdx.x;
    float a = b[j];
#pragma unroll 8
    for (int k = 0; k < K; k++) a = fmaf(sh[k], W[(size_t)k * Nout + j], a);
    if (dorelu) a = fmaxf(a, 0.f);
    out[g * Nout + j] = a;
}

__global__ void fc3_kernel(const float* __restrict__ in, const float* __restrict__ W,
                           const float* __restrict__ b, float* __restrict__ out) {
    int t = threadIdx.x;
    if (t >= Gg * 5) return;
    int g = t / 5, j = t % 5;
    float a = b[j];
    for (int k = 0; k < 256; k++) a = fmaf(in[g * 256 + k], W[k * 5 + j], a);
    out[g * 5 + j] = a;
}

// ---------------- host -------------------------------------------------------
extern "C" void kernel_launch(void* const* d_in, const int* in_sizes, int n_in,
                              void* d_out, int out_size) {
    (void)in_sizes; (void)n_in; (void)out_size;
    const float* x   = (const float*)d_in[0];
    const int*   ei  = (const int*)  d_in[1];
    const int*   bat = (const int*)  d_in[2];
    const float* W1  = (const float*)d_in[3];
    const float* as1 = (const float*)d_in[4];
    const float* ad1 = (const float*)d_in[5];
    const float* b1  = (const float*)d_in[6];
    const float* W2  = (const float*)d_in[7];
    const float* as2 = (const float*)d_in[8];
    const float* ad2 = (const float*)d_in[9];
    const float* b2  = (const float*)d_in[10];
    const float* Wc1 = (const float*)d_in[11];
    const float* bc1 = (const float*)d_in[12];
    const float* Wc2 = (const float*)d_in[13];
    const float* bc2 = (const float*)d_in[14];
    const float* Wc3 = (const float*)d_in[15];
    const float* bc3 = (const float*)d_in[16];
    float* out = (float*)d_out;

    float *ph, *px, *pes, *ped, *psum, *pmax, *ppool, *pf1, *pf2;
    int *pcnt, *pdeg, *poff, *pcur, *pcsr;
    __nv_bfloat16 *pwthi, *pwtlo, *pahi, *palo;
    cudaGetSymbolAddress((void**)&ph,   g_h);
    cudaGetSymbolAddress((void**)&px,   g_x);
    cudaGetSymbolAddress((void**)&pes,  g_esrc);
    cudaGetSymbolAddress((void**)&ped,  g_edst);
    cudaGetSymbolAddress((void**)&psum, g_sum);
    cudaGetSymbolAddress((void**)&pmax, g_max);
    cudaGetSymbolAddress((void**)&pcnt, g_cnt);
    cudaGetSymbolAddress((void**)&ppool,g_pool);
    cudaGetSymbolAddress((void**)&pf1,  g_fc1);
    cudaGetSymbolAddress((void**)&pf2,  g_fc2);
    cudaGetSymbolAddress((void**)&pwthi, g_wthi);
    cudaGetSymbolAddress((void**)&pwtlo, g_wtlo);
    cudaGetSymbolAddress((void**)&pahi, g_ahi);
    cudaGetSymbolAddress((void**)&palo, g_alo);
    cudaGetSymbolAddress((void**)&pdeg, g_deg);
    cudaGetSymbolAddress((void**)&poff, g_off);
    cudaGetSymbolAddress((void**)&pcur, g_cur);
    cudaGetSymbolAddress((void**)&pcsr, g_csr);

    cudaFuncSetAttribute(gemm_mma_kernel,
                         cudaFuncAttributeMaxDynamicSharedMemorySize, GEMM_SMEM);

    const int* src = ei;
    const int* dst = ei + Ee;

    const int GRID_E = (EP + 255) / 256;
    const int GRID_N = (Nn + 255) / 256;
    const dim3 gemm_grid(DH / 256, (Nn + 127) / 128);   // (4, 391)

    // ---- CSR build (graph is identical for both layers) ----
    csr_zero_kernel<<<GRID_N, 256>>>(pdeg, pcur);
    csr_hist_kernel<<<GRID_E, 256>>>(dst, pdeg);
    csr_scan_kernel<<<1, 1024>>>(pdeg, poff);
    csr_fill_kernel<<<GRID_E, 256>>>(src, dst, poff, pcur, pcsr);

    // ---- GAT layer 1 ----
    wsplit_kernel<<<(DIN * DH + 255) / 256, 256>>>(W1, pwthi, pwtlo, DIN);
    asplit_kernel<<<(Nn * DIN + 255) / 256, 256>>>(x, pahi, palo, Nn * DIN);
    gemm_mma_kernel<<<gemm_grid, 512, GEMM_SMEM>>>(pahi, palo, pwthi, pwtlo,
                                                   ph, Nn, DIN);
    scores_kernel<<<Nn, 128>>>(ph, as1, ad1, pes, ped);
    agg_kernel<<<Nn, 256>>>(poff, pcsr, pes, ped, ph, b1, px, pahi, palo);

    // ---- GAT layer 2 ----
    wsplit_kernel<<<(DH * DH + 255) / 256, 256>>>(W2, pwthi, pwtlo, DH);
    gemm_mma_kernel<<<gemm_grid, 512, GEMM_SMEM>>>(pahi, palo, pwthi, pwtlo,
                                                   ph, Nn, DH);
    scores_kernel<<<Nn, 128>>>(ph, as2, ad2, pes, ped);
    agg_kernel<<<Nn, 256>>>(poff, pcsr, pes, ped, ph, b2, px,
                            (__nv_bfloat16*)0, (__nv_bfloat16*)0);

    // ---- pooling ----
    pool_init_kernel<<<(Gg * DH + 255) / 256, 256>>>(psum, pmax, pcnt);
    count_kernel<<<GRID_N, 256>>>(bat, pcnt);
    pool_accum_kernel<<<dim3(DH / 256, (Nn + 127) / 128), 256>>>(px, bat, psum, pmax);
    pool_final_kernel<<<(Gg * DH + 255) / 256, 256>>>(psum, pmax, pcnt, ppool);

    // ---- classifier ----
    fc_kernel<<<Gg, 512>>>(ppool, Wc1, bc1, pf1, 2 * DH, 512, 1);
    fc_kernel<<<Gg, 256>>>(pf1, Wc2, bc2, pf2, 512, 256, 1);
    fc3_kernel<<<1, Gg * 5>>>(pf2, Wc3, bc3, out);
}

// round 12
// speedup vs baseline: 1.5006x; 1.0466x over previous
#include <cuda_runtime.h>
#include <cuda_bf16.h>
#include <math.h>
#include <stdint.h>

#define Nn   50000
#define Ee   200000
#define EP   (Ee + Nn)      // 250000 edges incl. self loops
#define Gg   64
#define Hh   4
#define Cch  256
#define DH   1024
#define DIN  768

// ---------------- scratch (device globals; no allocation allowed) ----------
__device__ float g_h  [(size_t)Nn * DH];   // x @ W  (current layer)
__device__ float g_x  [(size_t)Nn * DH];   // layer-2 output (post ELU)
__device__ float g_esrc[Nn * Hh];
__device__ float g_edst[Nn * Hh];
__device__ float g_sum [Gg * DH];
__device__ float g_max [Gg * DH];
__device__ int   g_cnt [Gg];
__device__ float g_pool[Gg * 2 * DH];
__device__ float g_fc1 [Gg * 512];
__device__ float g_fc2 [Gg * 256];
// transposed + hi/lo split weights: Wt[n][k]
__device__ __nv_bfloat16 g_wthi[(size_t)DH * DH];
__device__ __nv_bfloat16 g_wtlo[(size_t)DH * DH];
// hi/lo split activations (GEMM A operand)
__device__ __nv_bfloat16 g_ahi[(size_t)Nn * DH];
__device__ __nv_bfloat16 g_alo[(size_t)Nn * DH];
// CSR by destination
__device__ int g_deg[Nn];
__device__ int g_off[Nn + 1];
__device__ int g_cur[Nn];
__device__ int g_csr[EP];          // src node per slot

// ---------------- helpers ---------------------------------------------------
__device__ __forceinline__ float lrelu(float x) { return x > 0.f ? x : 0.2f * x; }
__device__ __forceinline__ float eluf (float x) { return x > 0.f ? x : expm1f(x); }

__device__ __forceinline__ void atomicMaxF(float* a, float v) {
    if (v >= 0.f) atomicMax((int*)a, __float_as_int(v));
    else          atomicMin((unsigned int*)a, __float_as_uint(v));
}

__device__ __forceinline__ uint32_t smem_u32(const void* p) {
    uint32_t a;
    asm("{ .reg .u64 t; cvta.to.shared.u64 t, %1; cvt.u32.u64 %0, t; }"
        : "=r"(a) : "l"(p));
    return a;
}

__device__ __forceinline__ void ldm4(uint32_t* r, uint32_t addr) {
    asm volatile("ldmatrix.sync.aligned.m8n8.x4.shared.b16 {%0,%1,%2,%3}, [%4];"
                 : "=r"(r[0]), "=r"(r[1]), "=r"(r[2]), "=r"(r[3]) : "r"(addr));
}

__device__ __forceinline__ void mma16816(float* c, const uint32_t* a,
                                         uint32_t b0, uint32_t b1) {
    asm volatile(
        "mma.sync.aligned.m16n8k16.row.col.f32.bf16.bf16.f32 "
        "{%0,%1,%2,%3}, {%4,%5,%6,%7}, {%8,%9}, {%0,%1,%2,%3};"
        : "+f"(c[0]), "+f"(c[1]), "+f"(c[2]), "+f"(c[3])
        : "r"(a[0]), "r"(a[1]), "r"(a[2]), "r"(a[3]), "r"(b0), "r"(b1));
}

#define CPA16(dst, src) \
    asm volatile("cp.async.cg.shared.global [%0], [%1], 16;" \
                 :: "r"(dst), "l"(src) : "memory")
#define CPA16Z(dst, src, szr) \
    asm volatile("cp.async.cg.shared.global [%0], [%1], 16, %2;" \
                 :: "r"(dst), "l"(src), "r"(szr) : "memory")

// ---------------- CSR build --------------------------------------------------
__global__ void csr_zero_kernel(int* __restrict__ deg, int* __restrict__ cur) {
    int i = blockIdx.x * 256 + threadIdx.x;
    if (i < Nn) { deg[i] = 0; cur[i] = 0; }
}

__global__ void csr_hist_kernel(const int* __restrict__ dst, int* __restrict__ deg) {
    int i = blockIdx.x * 256 + threadIdx.x;
    if (i >= EP) return;
    int d_ = (i < Ee) ? dst[i] : (i - Ee);
    atomicAdd(&deg[d_], 1);
}

__global__ void csr_scan_kernel(const int* __restrict__ deg, int* __restrict__ off) {
    __shared__ int bs[1024];
    const int t = threadIdx.x;
    const int per = (Nn + 1023) / 1024;        // 49
    const int b0 = t * per;
    int loc = 0;
    for (int i = 0; i < per; i++) {
        int idx = b0 + i;
        if (idx < Nn) loc += deg[idx];
    }
    bs[t] = loc;
    __syncthreads();
    for (int o = 1; o < 1024; o <<= 1) {
        int v = (t >= o) ? bs[t - o] : 0;
        __syncthreads();
        bs[t] += v;
        __syncthreads();
    }
    int run = t ? bs[t - 1] : 0;
    for (int i = 0; i < per; i++) {
        int idx = b0 + i;
        if (idx < Nn) { off[idx] = run; run += deg[idx]; }
    }
    if (t == 1023) off[Nn] = run;
}

__global__ void csr_fill_kernel(const int* __restrict__ src, const int* __restrict__ dst,
                                const int* __restrict__ off, int* __restrict__ cur,
                                int* __restrict__ csr) {
    int i = blockIdx.x * 256 + threadIdx.x;
    if (i >= EP) return;
    int s_, d_;
    if (i < Ee) { s_ = src[i]; d_ = dst[i]; } else { s_ = d_ = i - Ee; }
    int pos = off[d_] + atomicAdd(&cur[d_], 1);
    csr[pos] = s_;
}

// ---------------- splits -----------------------------------------------------
__global__ void wsplit_kernel(const float* __restrict__ W,
                              __nv_bfloat16* __restrict__ hi,
                              __nv_bfloat16* __restrict__ lo, int K) {
    int idx = blockIdx.x * 256 + threadIdx.x;
    if (idx >= K * DH) return;
    int n = idx & (DH - 1), k = idx >> 10;   // W[k][n], row-major (K, 1024)
    float v = W[idx];
    __nv_bfloat16 h = __float2bfloat16(v);
    hi[(size_t)n * K + k] = h;
    lo[(size_t)n * K + k] = __float2bfloat16(v - __bfloat162float(h));
}

__global__ void asplit_kernel(const float* __restrict__ A,
                              __nv_bfloat16* __restrict__ hi,
                              __nv_bfloat16* __restrict__ lo, int total) {
    int idx = blockIdx.x * 256 + threadIdx.x;
    if (idx >= total) return;
    float v = A[idx];
    __nv_bfloat16 h = __float2bfloat16(v);
    hi[idx] = h;
    lo[idx] = __float2bfloat16(v - __bfloat162float(h));
}

// ---------------- tensor-core GEMM via mma.sync (bf16x3 split) --------------
// C[M,1024] = A[M,K] @ W[K,1024]; fused attention-score epilogue:
// col tile == one head (N-tile 256), so this CTA computes es/ed for its rows.
#define GEMM_SMEM (2 * 98304)

__global__ __launch_bounds__(512, 1)
void gemm_mma_kernel(const __nv_bfloat16* __restrict__ Ahi,
                     const __nv_bfloat16* __restrict__ Alo,
                     const __nv_bfloat16* __restrict__ Bhi,
                     const __nv_bfloat16* __restrict__ Blo,
                     float* __restrict__ C, int M, int K,
                     const float* __restrict__ asrc,
                     const float* __restrict__ adst,
                     float* __restrict__ es, float* __restrict__ ed) {
    extern __shared__ __align__(1024) char smem[];
    const int tid = threadIdx.x, wid = tid >> 5, lane = tid & 31;
    const int wm = wid & 3, wn = wid >> 2;
    const int lr = lane & 15, lh = lane >> 4;
    const int row0 = blockIdx.y * 128, col0 = blockIdx.x * 256;
    const int head = blockIdx.x;               // 256-wide col tile == head
    const uint32_t sb = smem_u32(smem);
    const int nc = K >> 6;

    float acc[2][8][4];
#pragma unroll
    for (int t = 0; t < 2; t++)
#pragma unroll
        for (int j = 0; j < 8; j++)
#pragma unroll
            for (int q = 0; q < 4; q++) acc[t][j][q] = 0.f;

    auto loadStage = [&](int ck) {
        uint32_t st = sb + (uint32_t)(ck & 1) * 98304u;
        const __nv_bfloat16* Ah = Ahi + (size_t)row0 * K + ck * 64;
        const __nv_bfloat16* Al = Alo + (size_t)row0 * K + ck * 64;
#pragma unroll
        for (int u = tid; u < 1024; u += 512) {
            int r = u >> 3, c = u & 7;
            uint32_t d = st + (uint32_t)(r * 128) + (uint32_t)((c ^ (r & 7)) << 4);
            uint32_t sz = (row0 + r < M) ? 16u : 0u;
            CPA16Z(d,          Ah + (size_t)r * K + c * 8, sz);
            CPA16Z(d + 16384u, Al + (size_t)r * K + c * 8, sz);
        }
        const __nv_bfloat16* Bh = Bhi + (size_t)col0 * K + ck * 64;
        const __nv_bfloat16* Bl = Blo + (size_t)col0 * K + ck * 64;
#pragma unroll
        for (int u = tid; u < 2048; u += 512) {
            int r = u >> 3, c = u & 7;
            uint32_t d = st + 32768u + (uint32_t)(r * 128) +
                         (uint32_t)((c ^ (r & 7)) << 4);
            CPA16(d,          Bh + (size_t)r * K + c * 8);
            CPA16(d + 32768u, Bl + (size_t)r * K + c * 8);
        }
        asm volatile("cp.async.commit_group;" ::: "memory");
    };

    auto compute = [&](int ck) {
        uint32_t base = sb + (uint32_t)(ck & 1) * 98304u;
#pragma unroll
        for (int ks = 0; ks < 4; ks++) {
            uint32_t c16 = (uint32_t)(ks * 2 + lh);
            uint32_t ah[2][4], al[2][4];
#pragma unroll
            for (int t = 0; t < 2; t++) {
                int row = wm * 32 + t * 16 + lr;
                uint32_t ad = base + (uint32_t)(row * 128) +
                              ((c16 ^ (uint32_t)(row & 7)) << 4);
                ldm4(ah[t], ad);
                ldm4(al[t], ad + 16384u);
            }
#pragma unroll
            for (int g = 0; g < 4; g++) {
                int row = wn * 64 + g * 16 + lr;
                uint32_t bd = base + 32768u + (uint32_t)(row * 128) +
                              ((c16 ^ (uint32_t)(row & 7)) << 4);
                uint32_t bh[4], bl[4];
                ldm4(bh, bd);
                ldm4(bl, bd + 32768u);
#pragma unroll
                for (int t = 0; t < 2; t++)
#pragma unroll
                    for (int o = 0; o < 2; o++) {
                        float* a4 = acc[t][g * 2 + o];
                        mma16816(a4, ah[t], bh[o], bh[o + 2]);   // hi*hi
                        mma16816(a4, al[t], bh[o], bh[o + 2]);   // lo*hi
                        mma16816(a4, ah[t], bl[o], bl[o + 2]);   // hi*lo
                    }
            }
        }
    };

    // ---- prologue ----
    loadStage(0);
    if (nc > 1) loadStage(1);
    asm volatile("cp.async.wait_group %0;" :: "n"(1) : "memory");
    __syncthreads();

    // ---- mainloop ----
    for (int c = 0; c < nc; ++c) {
        compute(c);
        __syncthreads();
        if (c + 1 < nc) {
            if (c + 2 < nc) {
                loadStage(c + 2);
                asm volatile("cp.async.wait_group %0;" :: "n"(1) : "memory");
            } else {
                asm volatile("cp.async.wait_group %0;" :: "n"(0) : "memory");
            }
            __syncthreads();
        }
    }

    // ---- epilogue: C store + fused per-head attention scores ----
    float* sred = (float*)smem;                 // [0:128) src, [128:256) dst
#pragma unroll
    for (int i = tid; i < 256; i += 512) sred[i] = 0.f;

    float psum[2][2] = {{0.f, 0.f}, {0.f, 0.f}};
    float pdum[2][2] = {{0.f, 0.f}, {0.f, 0.f}};
#pragma unroll
    for (int t = 0; t < 2; t++) {
        int m0 = row0 + wm * 32 + t * 16 + (lane >> 2);
#pragma unroll
        for (int j = 0; j < 8; j++) {
            int cloc = wn * 64 + j * 8 + (lane & 3) * 2;
            int col = col0 + cloc;
            if (m0 < M)
                *(float2*)(C + (size_t)m0 * DH + col) =
                    make_float2(acc[t][j][0], acc[t][j][1]);
            if (m0 + 8 < M)
                *(float2*)(C + (size_t)(m0 + 8) * DH + col) =
                    make_float2(acc[t][j][2], acc[t][j][3]);
            float a0 = asrc[head * Cch + cloc], a1 = asrc[head * Cch + cloc + 1];
            float d0 = adst[head * Cch + cloc], d1 = adst[head * Cch + cloc + 1];
            psum[t][0] += acc[t][j][0] * a0 + acc[t][j][1] * a1;
            psum[t][1] += acc[t][j][2] * a0 + acc[t][j][3] * a1;
            pdum[t][0] += acc[t][j][0] * d0 + acc[t][j][1] * d1;
            pdum[t][1] += acc[t][j][2] * d0 + acc[t][j][3] * d1;
        }
    }
    // reduce over the 4 lanes of each quad (lane&3)
#pragma unroll
    for (int t = 0; t < 2; t++)
#pragma unroll
        for (int r2 = 0; r2 < 2; r2++) {
            psum[t][r2] += __shfl_xor_sync(0xffffffffu, psum[t][r2], 1);
            psum[t][r2] += __shfl_xor_sync(0xffffffffu, psum[t][r2], 2);
            pdum[t][r2] += __shfl_xor_sync(0xffffffffu, pdum[t][r2], 1);
            pdum[t][r2] += __shfl_xor_sync(0xffffffffu, pdum[t][r2], 2);
        }
    __syncthreads();            // sred zero-fill visible; stage reads long done
    if ((lane & 3) == 0) {
#pragma unroll
        for (int t = 0; t < 2; t++)
#pragma unroll
            for (int r2 = 0; r2 < 2; r2++) {
                int rl = wm * 32 + t * 16 + r2 * 8 + (lane >> 2);
                atomicAdd(&sred[rl],       psum[t][r2]);
                atomicAdd(&sred[128 + rl], pdum[t][r2]);
            }
    }
    __syncthreads();
#pragma unroll
    for (int r2 = tid; r2 < 128; r2 += 512) {
        int n = row0 + r2;
        if (n < M) {
            es[n * Hh + head] = sred[r2];
            ed[n * Hh + head] = sred[128 + r2];
        }
    }
}

// ---------------- fused softmax + gather aggregation -------------------------
// one 256-thread block per destination node; emits fp32 output unless the bf16
// hi/lo pair is requested (layer 1: only the split is consumed downstream).
__global__ __launch_bounds__(256)
void agg_kernel(const int* __restrict__ off, const int* __restrict__ csr,
                const float* __restrict__ es, const float* __restrict__ ed,
                const float* __restrict__ h, const float* __restrict__ bias,
                float* __restrict__ out,
                __nv_bfloat16* __restrict__ ohi, __nv_bfloat16* __restrict__ olo) {
    const int d = blockIdx.x;
    const int beg = off[d], end = off[d + 1];
    const int deg = end - beg;
    const int tid = threadIdx.x, wid = tid >> 5, lane = tid & 31;

    __shared__ float sm[4], ss[4];
    __shared__ float al[4][64];

    if (wid < 4) {
        const float edv = ed[d * 4 + wid];
        float mx = -INFINITY;
        for (int i = beg + lane; i < end; i += 32) {
            int s_ = csr[i];
            mx = fmaxf(mx, lrelu(es[s_ * 4 + wid] + edv));
        }
#pragma unroll
        for (int o = 16; o; o >>= 1)
            mx = fmaxf(mx, __shfl_xor_sync(0xffffffffu, mx, o));
        float su = 0.f;
        for (int i = beg + lane; i < end; i += 32) {
            int s_ = csr[i];
            su += expf(lrelu(es[s_ * 4 + wid] + edv) - mx);
        }
#pragma unroll
        for (int o = 16; o; o >>= 1)
            su += __shfl_xor_sync(0xffffffffu, su, o);
        if (lane == 0) { sm[wid] = mx; ss[wid] = su; }
    }
    __syncthreads();

    const int head = tid >> 6;
    float4 acc = make_float4(0.f, 0.f, 0.f, 0.f);

    for (int c0 = 0; c0 < deg; c0 += 64) {
        {
            int j = tid & 63, hh = tid >> 6;
            if (c0 + j < deg) {
                int s_ = csr[beg + c0 + j];
                float e = lrelu(es[s_ * 4 + hh] + ed[d * 4 + hh]);
                al[hh][j] = expf(e - sm[hh]) / (ss[hh] + 1e-16f);
            }
        }
        __syncthreads();
        int lim = min(64, deg - c0);
        for (int j = 0; j < lim; j++) {
            int s_ = csr[beg + c0 + j];
            float a = al[head][j];
            float4 v = *(const float4*)(h + (size_t)s_ * DH + tid * 4);
            acc.x = fmaf(a, v.x, acc.x);
            acc.y = fmaf(a, v.y, acc.y);
            acc.z = fmaf(a, v.z, acc.z);
            acc.w = fmaf(a, v.w, acc.w);
        }
        __syncthreads();
    }

    float4 bb = *(const float4*)(bias + tid * 4);
    acc.x = eluf(acc.x + bb.x);
    acc.y = eluf(acc.y + bb.y);
    acc.z = eluf(acc.z + bb.z);
    acc.w = eluf(acc.w + bb.w);

    if (ohi) {
        __nv_bfloat162 h0 = __floats2bfloat162_rn(acc.x, acc.y);
        __nv_bfloat162 h1 = __floats2bfloat162_rn(acc.z, acc.w);
        __nv_bfloat162 l0 = __floats2bfloat162_rn(acc.x - __bfloat162float(h0.x),
                                                  acc.y - __bfloat162float(h0.y));
        __nv_bfloat162 l1 = __floats2bfloat162_rn(acc.z - __bfloat162float(h1.x),
                                                  acc.w - __bfloat162float(h1.y));
        *(__nv_bfloat162*)(ohi + (size_t)d * DH + tid * 4)     = h0;
        *(__nv_bfloat162*)(ohi + (size_t)d * DH + tid * 4 + 2) = h1;
        *(__nv_bfloat162*)(olo + (size_t)d * DH + tid * 4)     = l0;
        *(__nv_bfloat162*)(olo + (size_t)d * DH + tid * 4 + 2) = l1;
    } else {
        *(float4*)(out + (size_t)d * DH + tid * 4) = acc;
    }
}

// ---------------- pooling ----------------------------------------------------
__global__ void pool_init_kernel(float* __restrict__ sum, float* __restrict__ mx,
                                 int* __restrict__ cnt) {
    int i = blockIdx.x * blockDim.x + threadIdx.x;
    if (i < Gg * DH) { sum[i] = 0.f; mx[i] = -INFINITY; }
    if (i < Gg) cnt[i] = 0;
}

__global__ void count_kernel(const int* __restrict__ batch, int* __restrict__ cnt) {
    int i = blockIdx.x * blockDim.x + threadIdx.x;
    if (i < Nn) atomicAdd(&cnt[batch[i]], 1);
}

__global__ void pool_accum_kernel(const float* __restrict__ x, const int* __restrict__ batch,
                                  float* __restrict__ gsum, float* __restrict__ gmax) {
    int c  = blockIdx.x * 256 + threadIdx.x;
    int n0 = blockIdx.y * 128;
    int n1 = min(n0 + 128, Nn);
    float sum = 0.f, mx = -INFINITY;
    int cur = batch[n0];
    for (int n = n0; n < n1; ++n) {
        int g = batch[n];
        if (g != cur) {
            atomicAdd(&gsum[cur * DH + c], sum);
            atomicMaxF(&gmax[cur * DH + c], mx);
            sum = 0.f; mx = -INFINITY; cur = g;
        }
        float v = x[(size_t)n * DH + c];
        sum += v; if (v > mx) mx = v;
    }
    atomicAdd(&gsum[cur * DH + c], sum);
    atomicMaxF(&gmax[cur * DH + c], mx);
}

__global__ void pool_final_kernel(const float* __restrict__ gsum, const float* __restrict__ gmax,
                                  const int* __restrict__ cnt, float* __restrict__ pool) {
    int i = blockIdx.x * blockDim.x + threadIdx.x;
    if (i >= Gg * DH) return;
    int g = i >> 10, c = i & (DH - 1);
    float cf = (float)cnt[g]; if (cf < 1.f) cf = 1.f;
    pool[g * 2 * DH + c] = gsum[i] / cf;
    float mv = gmax[i];
    pool[g * 2 * DH + DH + c] = isfinite(mv) ? mv : 0.f;
}

// ---------------- classifier -------------------------------------------------
__global__ void fc_kernel(const float* __restrict__ in, const float* __restrict__ W,
                          const float* __restrict__ b, float* __restrict__ out,
                          int K, int Nout, int dorelu) {
    __shared__ float sh[2048];
    int g = blockIdx.x;
    for (int k = threadIdx.x; k < K; k += blockDim.x) sh[k] = in[g * K + k];
    __syncthreads();
    int j = threadIdx.x;
    float a = b[j];
#pragma unroll 8
    for (int k = 0; k < K; k++) a = fmaf(sh[k], W[(size_t)k * Nout + j], a);
    if (dorelu) a = fmaxf(a, 0.f);
    out[g * Nout + j] = a;
}

__global__ void fc3_kernel(const float* __restrict__ in, const float* __restrict__ W,
                           const float* __restrict__ b, float* __restrict__ out) {
    int t = threadIdx.x;
    if (t >= Gg * 5) return;
    int g = t / 5, j = t % 5;
    float a = b[j];
    for (int k = 0; k < 256; k++) a = fmaf(in[g * 256 + k], W[k * 5 + j], a);
    out[g * 5 + j] = a;
}

// ---------------- host -------------------------------------------------------
extern "C" void kernel_launch(void* const* d_in, const int* in_sizes, int n_in,
                              void* d_out, int out_size) {
    (void)in_sizes; (void)n_in; (void)out_size;
    const float* x   = (const float*)d_in[0];
    const int*   ei  = (const int*)  d_in[1];
    const int*   bat = (const int*)  d_in[2];
    const float* W1  = (const float*)d_in[3];
    const float* as1 = (const float*)d_in[4];
    const float* ad1 = (const float*)d_in[5];
    const float* b1  = (const float*)d_in[6];
    const float* W2  = (const float*)d_in[7];
    const float* as2 = (const float*)d_in[8];
    const float* ad2 = (const float*)d_in[9];
    const float* b2  = (const float*)d_in[10];
    const float* Wc1 = (const float*)d_in[11];
    const float* bc1 = (const float*)d_in[12];
    const float* Wc2 = (const float*)d_in[13];
    const float* bc2 = (const float*)d_in[14];
    const float* Wc3 = (const float*)d_in[15];
    const float* bc3 = (const float*)d_in[16];
    float* out = (float*)d_out;

    float *ph, *px, *pes, *ped, *psum, *pmax, *ppool, *pf1, *pf2;
    int *pcnt, *pdeg, *poff, *pcur, *pcsr;
    __nv_bfloat16 *pwthi, *pwtlo, *pahi, *palo;
    cudaGetSymbolAddress((void**)&ph,   g_h);
    cudaGetSymbolAddress((void**)&px,   g_x);
    cudaGetSymbolAddress((void**)&pes,  g_esrc);
    cudaGetSymbolAddress((void**)&ped,  g_edst);
    cudaGetSymbolAddress((void**)&psum, g_sum);
    cudaGetSymbolAddress((void**)&pmax, g_max);
    cudaGetSymbolAddress((void**)&pcnt, g_cnt);
    cudaGetSymbolAddress((void**)&ppool,g_pool);
    cudaGetSymbolAddress((void**)&pf1,  g_fc1);
    cudaGetSymbolAddress((void**)&pf2,  g_fc2);
    cudaGetSymbolAddress((void**)&pwthi, g_wthi);
    cudaGetSymbolAddress((void**)&pwtlo, g_wtlo);
    cudaGetSymbolAddress((void**)&pahi, g_ahi);
    cudaGetSymbolAddress((void**)&palo, g_alo);
    cudaGetSymbolAddress((void**)&pdeg, g_deg);
    cudaGetSymbolAddress((void**)&poff, g_off);
    cudaGetSymbolAddress((void**)&pcur, g_cur);
    cudaGetSymbolAddress((void**)&pcsr, g_csr);

    cudaFuncSetAttribute(gemm_mma_kernel,
                         cudaFuncAttributeMaxDynamicSharedMemorySize, GEMM_SMEM);

    const int* src = ei;
    const int* dst = ei + Ee;

    const int GRID_E = (EP + 255) / 256;
    const int GRID_N = (Nn + 255) / 256;
    const dim3 gemm_grid(DH / 256, (Nn + 127) / 128);   // (4, 391)

    // ---- CSR build (graph is identical for both layers) ----
    csr_zero_kernel<<<GRID_N, 256>>>(pdeg, pcur);
    csr_hist_kernel<<<GRID_E, 256>>>(dst, pdeg);
    csr_scan_kernel<<<1, 1024>>>(pdeg, poff);
    csr_fill_kernel<<<GRID_E, 256>>>(src, dst, poff, pcur, pcsr);

    // ---- GAT layer 1 ----
    wsplit_kernel<<<(DIN * DH + 255) / 256, 256>>>(W1, pwthi, pwtlo, DIN);
    asplit_kernel<<<(Nn * DIN + 255) / 256, 256>>>(x, pahi, palo, Nn * DIN);
    gemm_mma_kernel<<<gemm_grid, 512, GEMM_SMEM>>>(pahi, palo, pwthi, pwtlo,
                                                   ph, Nn, DIN,
                                                   as1, ad1, pes, ped);
    agg_kernel<<<Nn, 256>>>(poff, pcsr, pes, ped, ph, b1, (float*)0, pahi, palo);

    // ---- GAT layer 2 ----
    wsplit_kernel<<<(DH * DH + 255) / 256, 256>>>(W2, pwthi, pwtlo, DH);
    gemm_mma_kernel<<<gemm_grid, 512, GEMM_SMEM>>>(pahi, palo, pwthi, pwtlo,
                                                   ph, Nn, DH,
                                                   as2, ad2, pes, ped);
    agg_kernel<<<Nn, 256>>>(poff, pcsr, pes, ped, ph, b2, px,
                            (__nv_bfloat16*)0, (__nv_bfloat16*)0);

    // ---- pooling ----
    pool_init_kernel<<<(Gg * DH + 255) / 256, 256>>>(psum, pmax, pcnt);
    count_kernel<<<GRID_N, 256>>>(bat, pcnt);
    pool_accum_kernel<<<dim3(DH / 256, (Nn + 127) / 128), 256>>>(px, bat, psum, pmax);
    pool_final_kernel<<<(Gg * DH + 255) / 256, 256>>>(psum, pmax, pcnt, ppool);

    // ---- classifier ----
    fc_kernel<<<Gg, 512>>>(ppool, Wc1, bc1, pf1, 2 * DH, 512, 1);
    fc_kernel<<<Gg, 256>>>(pf1, Wc2, bc2, pf2, 512, 256, 1);
    fc3_kernel<<<1, Gg * 5>>>(pf2, Wc3, bc3, out);
}